// round 4
// baseline (speedup 1.0000x reference)
#include <cuda_runtime.h>
#include <cuda_bf16.h>

// ---------------------------------------------------------------------------
// Problem constants
// ---------------------------------------------------------------------------
#define NTOK 4096
#define CB   32
#define CIN  64
#define BATCH 2

#define QT     128                     // queries per block (8 warps x 16 rows)
#define KTILE  64                      // keys per tile
#define SPLITS 2
#define KTILES (NTOK / SPLITS / KTILE) // 32
#define KP     40                      // padded row stride (bf16 elems)
#define KPB    80                      // padded row stride bytes

// Dynamic SMEM layout (bytes)
#define OFF_QH   0
#define OFF_QL   10240
#define OFF_BUF  20480
#define BUF_SZ   20480
#define BKH      0
#define BKL      5120
#define BVH      10240
#define BVL      15360
#define SMEM_BYTES (OFF_BUF + 2 * BUF_SZ)   // 61440

// ---------------------------------------------------------------------------
// Scratch (no cudaMalloc allowed)
// ---------------------------------------------------------------------------
__device__ __align__(16) __nv_bfloat16 g_gh[BATCH * NTOK * CB];
__device__ __align__(16) __nv_bfloat16 g_gl[BATCH * NTOK * CB];
__device__ __align__(16) __nv_bfloat16 g_fh[BATCH * NTOK * CB];
__device__ __align__(16) __nv_bfloat16 g_fl[BATCH * NTOK * CB];
__device__ __align__(16) __nv_bfloat16 g_hh[BATCH * NTOK * CB];
__device__ __align__(16) __nv_bfloat16 g_hl[BATCH * NTOK * CB];
__device__ __align__(16) float g_part[SPLITS][BATCH * NTOK * CB];
__device__ __align__(16) float g_m[SPLITS][BATCH * NTOK];
__device__ __align__(16) float g_l[SPLITS][BATCH * NTOK];

// ---------------------------------------------------------------------------
// Helpers
// ---------------------------------------------------------------------------
__device__ __forceinline__ unsigned smem_u32(const void* p) {
    unsigned a;
    asm("{ .reg .u64 t; cvta.to.shared.u64 t, %1; cvt.u32.u64 %0, t; }"
        : "=r"(a) : "l"(p));
    return a;
}
__device__ __forceinline__ void cp16(unsigned dst, const void* src) {
    asm volatile("cp.async.cg.shared.global [%0], [%1], 16;"
                 :: "r"(dst), "l"(src) : "memory");
}
#define CP_COMMIT() asm volatile("cp.async.commit_group;" ::: "memory")
#define CP_WAIT1()  asm volatile("cp.async.wait_group 1;" ::: "memory")

#define LDMX4(r, a) \
    asm volatile("ldmatrix.sync.aligned.m8n8.x4.shared.b16 {%0,%1,%2,%3}, [%4];" \
        : "=r"((r)[0]), "=r"((r)[1]), "=r"((r)[2]), "=r"((r)[3]) : "r"(a))
#define LDMX4T(r, a) \
    asm volatile("ldmatrix.sync.aligned.m8n8.x4.trans.shared.b16 {%0,%1,%2,%3}, [%4];" \
        : "=r"((r)[0]), "=r"((r)[1]), "=r"((r)[2]), "=r"((r)[3]) : "r"(a))

__device__ __forceinline__ void mma16816(float* d, const unsigned* a, const unsigned* b) {
    asm volatile(
        "mma.sync.aligned.m16n8k16.row.col.f32.bf16.bf16.f32 "
        "{%0,%1,%2,%3}, {%4,%5,%6,%7}, {%8,%9}, {%0,%1,%2,%3};"
        : "+f"(d[0]), "+f"(d[1]), "+f"(d[2]), "+f"(d[3])
        : "r"(a[0]), "r"(a[1]), "r"(a[2]), "r"(a[3]), "r"(b[0]), "r"(b[1]));
}

__device__ __forceinline__ void cvt_pair(float f0, float f1, unsigned& hi, unsigned& lo) {
    __nv_bfloat162 h = __floats2bfloat162_rn(f0, f1);
    float r0 = f0 - __bfloat162float(h.x);
    float r1 = f1 - __bfloat162float(h.y);
    __nv_bfloat162 l = __floats2bfloat162_rn(r0, r1);
    hi = *(unsigned*)&h;
    lo = *(unsigned*)&l;
}

// ---------------------------------------------------------------------------
// Kernel 1: projections -> packed bf16 hi/lo arrays (split done ONCE here)
// ---------------------------------------------------------------------------
__global__ __launch_bounds__(256) void proj_kernel(
    const float* __restrict__ x,
    const float* __restrict__ Wf, const float* __restrict__ bf,
    const float* __restrict__ Wg, const float* __restrict__ bg,
    const float* __restrict__ Wh, const float* __restrict__ bh)
{
    int idx = blockIdx.x * blockDim.x + threadIdx.x;   // [0, B*N*8)
    int row = idx >> 3;
    int c4  = (idx & 7) * 4;
    const float4* xr = (const float4*)(x + (size_t)row * CIN);
    float4 af = *(const float4*)(bf + c4);
    float4 ag = *(const float4*)(bg + c4);
    float4 ah = *(const float4*)(bh + c4);
#pragma unroll 4
    for (int k4 = 0; k4 < CIN / 4; k4++) {
        float4 xv = xr[k4];
        float xs[4] = {xv.x, xv.y, xv.z, xv.w};
#pragma unroll
        for (int j = 0; j < 4; j++) {
            int k = k4 * 4 + j;
            float4 wf = *(const float4*)(Wf + k * CB + c4);
            float4 wg = *(const float4*)(Wg + k * CB + c4);
            float4 wh = *(const float4*)(Wh + k * CB + c4);
            af.x = fmaf(xs[j], wf.x, af.x); af.y = fmaf(xs[j], wf.y, af.y);
            af.z = fmaf(xs[j], wf.z, af.z); af.w = fmaf(xs[j], wf.w, af.w);
            ag.x = fmaf(xs[j], wg.x, ag.x); ag.y = fmaf(xs[j], wg.y, ag.y);
            ag.z = fmaf(xs[j], wg.z, ag.z); ag.w = fmaf(xs[j], wg.w, ag.w);
            ah.x = fmaf(xs[j], wh.x, ah.x); ah.y = fmaf(xs[j], wh.y, ah.y);
            ah.z = fmaf(xs[j], wh.z, ah.z); ah.w = fmaf(xs[j], wh.w, ah.w);
        }
    }
    size_t o = (size_t)row * CB + c4;
    unsigned h0, l0, h1, l1;
    cvt_pair(af.x, af.y, h0, l0); cvt_pair(af.z, af.w, h1, l1);
    *(uint2*)(g_fh + o) = make_uint2(h0, h1);
    *(uint2*)(g_fl + o) = make_uint2(l0, l1);
    cvt_pair(ag.x, ag.y, h0, l0); cvt_pair(ag.z, ag.w, h1, l1);
    *(uint2*)(g_gh + o) = make_uint2(h0, h1);
    *(uint2*)(g_gl + o) = make_uint2(l0, l1);
    cvt_pair(ah.x, ah.y, h0, l0); cvt_pair(ah.z, ah.w, h1, l1);
    *(uint2*)(g_hh + o) = make_uint2(h0, h1);
    *(uint2*)(g_hl + o) = make_uint2(l0, l1);
}

// ---------------------------------------------------------------------------
// Kernel 2: flash attention, mma.sync bf16 3-pass split, cp.async double-buffer
// ---------------------------------------------------------------------------
__global__ __launch_bounds__(256, 1) void attn_kernel()
{
    extern __shared__ __align__(16) unsigned char smem[];
    const unsigned sbase = smem_u32(smem);

    const int b  = blockIdx.y;
    const int q0 = blockIdx.x * QT;
    const int k0 = blockIdx.z * (NTOK / SPLITS);
    const int t  = threadIdx.x;
    const int w  = t >> 5;
    const int lane = t & 31;

    // staging indices
    const int qrow = t >> 1, qhalf = t & 1;                  // Q staging
    const int krow = t >> 2, kq = t & 3;                     // K/V staging
    const size_t qoff = (size_t)(b * NTOK + q0 + qrow) * CB + qhalf * 16;
    const unsigned qdH = sbase + OFF_QH + qrow * KPB + qhalf * 32;
    const unsigned qdL = sbase + OFF_QL + qrow * KPB + qhalf * 32;

    // ---- Prologue: group g0 = Q + tile0, group g1 = tile1 ----------------
    cp16(qdH,      g_gh + qoff);
    cp16(qdH + 16, g_gh + qoff + 8);
    cp16(qdL,      g_gl + qoff);
    cp16(qdL + 16, g_gl + qoff + 8);
    {
        size_t goff = (size_t)(b * NTOK + k0 + krow) * CB + kq * 8;
        unsigned so = sbase + OFF_BUF + krow * KPB + kq * 16;
        cp16(so + BKH, g_fh + goff);
        cp16(so + BKL, g_fl + goff);
        cp16(so + BVH, g_hh + goff);
        cp16(so + BVL, g_hl + goff);
    }
    CP_COMMIT();
    {
        size_t goff = (size_t)(b * NTOK + k0 + KTILE + krow) * CB + kq * 8;
        unsigned so = sbase + OFF_BUF + BUF_SZ + krow * KPB + kq * 16;
        cp16(so + BKH, g_fh + goff);
        cp16(so + BKL, g_fl + goff);
        cp16(so + BVH, g_hh + goff);
        cp16(so + BVL, g_hl + goff);
    }
    CP_COMMIT();

    unsigned qh[2][4], ql[2][4];
    float m0 = -1e30f, m1 = -1e30f, l0 = 0.f, l1 = 0.f;
    float o[4][4];
#pragma unroll
    for (int nn = 0; nn < 4; nn++)
#pragma unroll
        for (int j = 0; j < 4; j++) o[nn][j] = 0.f;

    for (int kt = 0; kt < KTILES; kt++) {
        CP_WAIT1();            // groups g0..g_kt complete
        __syncthreads();

        if (kt == 0) {
            // Load Q fragments (persist in registers)
            unsigned qa = sbase + OFF_QH + (w * 16 + (lane & 15)) * KPB + (lane >> 4) * 16;
            unsigned qb = sbase + OFF_QL + (w * 16 + (lane & 15)) * KPB + (lane >> 4) * 16;
            LDMX4(qh[0], qa);
            LDMX4(qh[1], qa + 32);
            LDMX4(ql[0], qb);
            LDMX4(ql[1], qb + 32);
        }

        const unsigned bufb = sbase + OFF_BUF + (kt & 1) * BUF_SZ;
        const unsigned kaddr_h = bufb + BKH + (lane & 7) * KPB + (lane >> 3) * 16;
        const unsigned kaddr_l = bufb + BKL + (lane & 7) * KPB + (lane >> 3) * 16;
        const unsigned vbase_h = bufb + BVH + lane * KPB;
        const unsigned vbase_l = bufb + BVL + lane * KPB;

        // ---- GEMM1: S[16 x 64] = Q . K^T (3-pass bf16 split) -------------
        float s[8][4];
#pragma unroll
        for (int n = 0; n < 8; n++) {
            s[n][0] = s[n][1] = s[n][2] = s[n][3] = 0.f;
            unsigned kh[4], kl[4];
            LDMX4(kh, kaddr_h + n * 8 * KPB);
            LDMX4(kl, kaddr_l + n * 8 * KPB);
            mma16816(s[n], qh[0], kh + 0);
            mma16816(s[n], qh[1], kh + 2);
            mma16816(s[n], ql[0], kh + 0);
            mma16816(s[n], ql[1], kh + 2);
            mma16816(s[n], qh[0], kl + 0);
            mma16816(s[n], qh[1], kl + 2);
        }

        // ---- Online softmax ----------------------------------------------
        float r0 = -1e30f, r1 = -1e30f;
#pragma unroll
        for (int n = 0; n < 8; n++) {
            r0 = fmaxf(r0, fmaxf(s[n][0], s[n][1]));
            r1 = fmaxf(r1, fmaxf(s[n][2], s[n][3]));
        }
        r0 = fmaxf(r0, __shfl_xor_sync(0xffffffffu, r0, 1));
        r0 = fmaxf(r0, __shfl_xor_sync(0xffffffffu, r0, 2));
        r1 = fmaxf(r1, __shfl_xor_sync(0xffffffffu, r1, 1));
        r1 = fmaxf(r1, __shfl_xor_sync(0xffffffffu, r1, 2));
        float mn0 = fmaxf(m0, r0), mn1 = fmaxf(m1, r1);
        float al0 = __expf(m0 - mn0), al1 = __expf(m1 - mn1);

        float ps0 = 0.f, ps1 = 0.f;
        unsigned ph[4][4], pl[4][4];
#pragma unroll
        for (int n = 0; n < 8; n++) {
            float p0 = __expf(s[n][0] - mn0);
            float p1 = __expf(s[n][1] - mn0);
            float p2 = __expf(s[n][2] - mn1);
            float p3 = __expf(s[n][3] - mn1);
            ps0 += p0 + p1;  ps1 += p2 + p3;
            int kk = n >> 1, hset = (n & 1) * 2;
            cvt_pair(p0, p1, ph[kk][hset + 0], pl[kk][hset + 0]);
            cvt_pair(p2, p3, ph[kk][hset + 1], pl[kk][hset + 1]);
        }
        ps0 += __shfl_xor_sync(0xffffffffu, ps0, 1);
        ps0 += __shfl_xor_sync(0xffffffffu, ps0, 2);
        ps1 += __shfl_xor_sync(0xffffffffu, ps1, 1);
        ps1 += __shfl_xor_sync(0xffffffffu, ps1, 2);
        l0 = l0 * al0 + ps0;  l1 = l1 * al1 + ps1;
        m0 = mn0;  m1 = mn1;

#pragma unroll
        for (int nn = 0; nn < 4; nn++) {
            o[nn][0] *= al0; o[nn][1] *= al0;
            o[nn][2] *= al1; o[nn][3] *= al1;
        }

        // ---- GEMM2: O += P . V (3-pass split) -----------------------------
#pragma unroll
        for (int kkp = 0; kkp < 2; kkp++) {
            int kk0 = kkp * 2, kk1 = kkp * 2 + 1;
#pragma unroll
            for (int nn = 0; nn < 4; nn++) {
                unsigned vh[4], vl[4];
                unsigned off = (unsigned)(kkp * 32 * KPB + nn * 16);
                LDMX4T(vh, vbase_h + off);
                LDMX4T(vl, vbase_l + off);
                mma16816(o[nn], ph[kk0], vh + 0);
                mma16816(o[nn], ph[kk1], vh + 2);
                mma16816(o[nn], pl[kk0], vh + 0);
                mma16816(o[nn], pl[kk1], vh + 2);
                mma16816(o[nn], ph[kk0], vl + 0);
                mma16816(o[nn], ph[kk1], vl + 2);
            }
        }

        // ---- All warps done reading buf[kt&1]; refill it with tile kt+2 ---
        __syncthreads();
        if (kt + 2 < KTILES) {
            size_t goff = (size_t)(b * NTOK + k0 + (kt + 2) * KTILE + krow) * CB + kq * 8;
            unsigned so = bufb + krow * KPB + kq * 16;
            cp16(so + BKH, g_fh + goff);
            cp16(so + BKL, g_fl + goff);
            cp16(so + BVH, g_hh + goff);
            cp16(so + BVL, g_hl + goff);
        }
        CP_COMMIT();   // always commit: keeps wait_group accounting exact
    }

    // ---- Epilogue: store unnormalized partial + m, l ----------------------
    {
        int z = blockIdx.z;
        int r = lane >> 2;
        int c = (lane & 3) * 2;
        int grow0 = b * NTOK + q0 + w * 16 + r;
        int grow1 = grow0 + 8;
        if ((lane & 3) == 0) {
            g_m[z][grow0] = m0;  g_l[z][grow0] = l0;
            g_m[z][grow1] = m1;  g_l[z][grow1] = l1;
        }
#pragma unroll
        for (int nn = 0; nn < 4; nn++) {
            *(float2*)&g_part[z][(size_t)grow0 * CB + nn * 8 + c] = make_float2(o[nn][0], o[nn][1]);
            *(float2*)&g_part[z][(size_t)grow1 * CB + nn * 8 + c] = make_float2(o[nn][2], o[nn][3]);
        }
    }
}

// ---------------------------------------------------------------------------
// Kernel 3: fused combine + output projection + residual.
// 32 threads per row: (sub&15) -> 4 output cols, (sub>>4) -> k half.
// Partner lanes (lane ^ 16) shfl-reduce the two k halves.
// ---------------------------------------------------------------------------
__global__ __launch_bounds__(256) void outc_kernel(
    const float* __restrict__ x,
    const float* __restrict__ Wo, const float* __restrict__ bo,
    const float* __restrict__ gamma,
    float* __restrict__ out)
{
    int idx = blockIdx.x * blockDim.x + threadIdx.x;   // [0, B*N*32)
    int row = idx >> 5;
    int sub = idx & 31;
    int c4  = (sub & 15) * 4;
    int kh  = sub >> 4;            // k half: 0 -> k[0:16), 1 -> k[16:32)

    float m0 = g_m[0][row], m1 = g_m[1][row];
    float l0 = g_l[0][row], l1 = g_l[1][row];
    float M  = fmaxf(m0, m1);
    float w0 = __expf(m0 - M), w1 = __expf(m1 - M);
    float inv = 1.0f / (l0 * w0 + l1 * w1);
    w0 *= inv;  w1 *= inv;

    const float4* p0r = (const float4*)(&g_part[0][0] + (size_t)row * CB + kh * 16);
    const float4* p1r = (const float4*)(&g_part[1][0] + (size_t)row * CB + kh * 16);

    float4 o = make_float4(0.f, 0.f, 0.f, 0.f);
#pragma unroll
    for (int j4 = 0; j4 < 4; j4++) {
        float4 a = p0r[j4], bb = p1r[j4];
        float bs[4] = {a.x * w0 + bb.x * w1, a.y * w0 + bb.y * w1,
                       a.z * w0 + bb.z * w1, a.w * w0 + bb.w * w1};
#pragma unroll
        for (int j = 0; j < 4; j++) {
            float4 wv = *(const float4*)(Wo + (kh * 16 + j4 * 4 + j) * CIN + c4);
            o.x = fmaf(bs[j], wv.x, o.x);
            o.y = fmaf(bs[j], wv.y, o.y);
            o.z = fmaf(bs[j], wv.z, o.z);
            o.w = fmaf(bs[j], wv.w, o.w);
        }
    }
    // combine k halves across partner lanes (lane ^ 16)
    o.x += __shfl_xor_sync(0xffffffffu, o.x, 16);
    o.y += __shfl_xor_sync(0xffffffffu, o.y, 16);
    o.z += __shfl_xor_sync(0xffffffffu, o.z, 16);
    o.w += __shfl_xor_sync(0xffffffffu, o.w, 16);

    if (kh == 0) {
        float gm = gamma[0];
        float4 bv = *(const float4*)(bo + c4);
        float4 xv = *(const float4*)(x + (size_t)row * CIN + c4);
        float4 r;
        r.x = xv.x + gm * (o.x + bv.x);
        r.y = xv.y + gm * (o.y + bv.y);
        r.z = xv.z + gm * (o.z + bv.z);
        r.w = xv.w + gm * (o.w + bv.w);
        *(float4*)(out + (size_t)row * CIN + c4) = r;
    }
}

// ---------------------------------------------------------------------------
extern "C" void kernel_launch(void* const* d_in, const int* in_sizes, int n_in,
                              void* d_out, int out_size)
{
    const float* x     = (const float*)d_in[0];
    const float* Wf    = (const float*)d_in[1];
    const float* bf    = (const float*)d_in[2];
    const float* Wg    = (const float*)d_in[3];
    const float* bg    = (const float*)d_in[4];
    const float* Wh    = (const float*)d_in[5];
    const float* bh    = (const float*)d_in[6];
    const float* Wo    = (const float*)d_in[7];
    const float* bo    = (const float*)d_in[8];
    const float* gamma = (const float*)d_in[9];
    float* out = (float*)d_out;
    (void)in_sizes; (void)n_in; (void)out_size;

    cudaFuncSetAttribute(attn_kernel,
                         cudaFuncAttributeMaxDynamicSharedMemorySize, SMEM_BYTES);

    proj_kernel<<<BATCH * NTOK * 8 / 256, 256>>>(x, Wf, bf, Wg, bg, Wh, bh);

    dim3 agrid(NTOK / QT, BATCH, SPLITS);
    attn_kernel<<<agrid, 256, SMEM_BYTES>>>();

    outc_kernel<<<BATCH * NTOK * 32 / 256, 256>>>(x, Wo, bo, gamma, out);
}

// round 6
// speedup vs baseline: 1.1280x; 1.1280x over previous
#include <cuda_runtime.h>
#include <cuda_bf16.h>

// ---------------------------------------------------------------------------
// Problem constants
// ---------------------------------------------------------------------------
#define NTOK 4096
#define CB   32
#define CIN  64
#define BATCH 2

#define QT     128                     // queries per block (8 warps x 16 rows)
#define KTILE  64                      // keys per tile
#define SPLITS 2
#define KTILES (NTOK / SPLITS / KTILE) // 32
#define KP     40                      // padded row stride (bf16 elems)
#define KPB    80                      // padded row stride bytes

// attn dynamic SMEM layout (bytes)
#define OFF_QH   0
#define OFF_QL   10240
#define OFF_BUF  20480
#define BUF_SZ   20480
#define BKH      0
#define BKL      5120
#define BVH      10240
#define BVL      15360
#define SMEM_BYTES (OFF_BUF + 2 * BUF_SZ)   // 61440

// proj tiling
#define PROWS 64                       // rows per proj block
#define PWP   72                       // padded row stride (bf16) = 144B, odd mult of 16B
#define NPROJ 96                       // 3 * 32 output cols

// ---------------------------------------------------------------------------
// Scratch (no cudaMalloc allowed)
// ---------------------------------------------------------------------------
__device__ __align__(16) __nv_bfloat16 g_gh[BATCH * NTOK * CB];
__device__ __align__(16) __nv_bfloat16 g_gl[BATCH * NTOK * CB];
__device__ __align__(16) __nv_bfloat16 g_fh[BATCH * NTOK * CB];
__device__ __align__(16) __nv_bfloat16 g_fl[BATCH * NTOK * CB];
__device__ __align__(16) __nv_bfloat16 g_hh[BATCH * NTOK * CB];
__device__ __align__(16) __nv_bfloat16 g_hl[BATCH * NTOK * CB];
__device__ __align__(16) float g_part[SPLITS][BATCH * NTOK * CB];
__device__ __align__(16) float g_m[SPLITS][BATCH * NTOK];
__device__ __align__(16) float g_l[SPLITS][BATCH * NTOK];

// ---------------------------------------------------------------------------
// Helpers
// ---------------------------------------------------------------------------
__device__ __forceinline__ unsigned smem_u32(const void* p) {
    unsigned a;
    asm("{ .reg .u64 t; cvta.to.shared.u64 t, %1; cvt.u32.u64 %0, t; }"
        : "=r"(a) : "l"(p));
    return a;
}
__device__ __forceinline__ void cp16(unsigned dst, const void* src) {
    asm volatile("cp.async.cg.shared.global [%0], [%1], 16;"
                 :: "r"(dst), "l"(src) : "memory");
}
#define CP_COMMIT() asm volatile("cp.async.commit_group;" ::: "memory")
#define CP_WAIT1()  asm volatile("cp.async.wait_group 1;" ::: "memory")

#define LDMX4(r, a) \
    asm volatile("ldmatrix.sync.aligned.m8n8.x4.shared.b16 {%0,%1,%2,%3}, [%4];" \
        : "=r"((r)[0]), "=r"((r)[1]), "=r"((r)[2]), "=r"((r)[3]) : "r"(a))
#define LDMX4T(r, a) \
    asm volatile("ldmatrix.sync.aligned.m8n8.x4.trans.shared.b16 {%0,%1,%2,%3}, [%4];" \
        : "=r"((r)[0]), "=r"((r)[1]), "=r"((r)[2]), "=r"((r)[3]) : "r"(a))

__device__ __forceinline__ void mma16816(float* d, const unsigned* a, const unsigned* b) {
    asm volatile(
        "mma.sync.aligned.m16n8k16.row.col.f32.bf16.bf16.f32 "
        "{%0,%1,%2,%3}, {%4,%5,%6,%7}, {%8,%9}, {%0,%1,%2,%3};"
        : "+f"(d[0]), "+f"(d[1]), "+f"(d[2]), "+f"(d[3])
        : "r"(a[0]), "r"(a[1]), "r"(a[2]), "r"(a[3]), "r"(b[0]), "r"(b[1]));
}

__device__ __forceinline__ void cvt_pair(float f0, float f1, unsigned& hi, unsigned& lo) {
    __nv_bfloat162 h = __floats2bfloat162_rn(f0, f1);
    float r0 = f0 - __bfloat162float(h.x);
    float r1 = f1 - __bfloat162float(h.y);
    __nv_bfloat162 l = __floats2bfloat162_rn(r0, r1);
    hi = *(unsigned*)&h;
    lo = *(unsigned*)&l;
}

// ---------------------------------------------------------------------------
// Kernel 1: projections as one HMMA GEMM: [B*N x 64] @ [64 x 96] + bias,
// written straight into the packed bf16 hi/lo arrays attn consumes.
// ---------------------------------------------------------------------------
__global__ __launch_bounds__(128) void proj_mma_kernel(
    const float* __restrict__ x,
    const float* __restrict__ Wf, const float* __restrict__ bf,
    const float* __restrict__ Wg, const float* __restrict__ bg,
    const float* __restrict__ Wh, const float* __restrict__ bh)
{
    __shared__ __nv_bfloat16 sXh[PROWS * PWP], sXl[PROWS * PWP];   // 18432 B
    __shared__ __nv_bfloat16 sWh[NPROJ * PWP], sWl[NPROJ * PWP];   // 27648 B

    const int t    = threadIdx.x;
    const int w    = t >> 5;
    const int lane = t & 31;
    const int row0 = blockIdx.x * PROWS;        // global row base (over B*N)

    // ---- Stage x tile: thread = (row, half), 8 float4 each ----------------
    {
        int r = t >> 1, half = t & 1;
        const float4* src = (const float4*)(x + (size_t)(row0 + r) * CIN + half * 32);
        int e = r * PWP + half * 32;
#pragma unroll
        for (int i = 0; i < 8; i++) {
            float4 v = src[i];
            unsigned h0, l0, h1, l1;
            cvt_pair(v.x, v.y, h0, l0);
            cvt_pair(v.z, v.w, h1, l1);
            *(uint2*)(sXh + e + i * 4) = make_uint2(h0, h1);
            *(uint2*)(sXl + e + i * 4) = make_uint2(l0, l1);
        }
    }

    // ---- Stage W transposed: sW[c + 32p][k] = Wp[k*32 + c] ----------------
    {
        const float* Ws[3] = {Wf, Wg, Wh};
#pragma unroll
        for (int it = 0; it < 12; it++) {
            int i = t + it * 128;                 // [0, 1536) float4 index
            int p = i >> 9;                       // /512
            int rr = i & 511;
            int k = rr >> 3;
            int c = (rr & 7) * 4;
            float4 v = *(const float4*)(Ws[p] + k * CB + c);
            int cb = p * CB + c;
            unsigned h, l;
            cvt_pair(v.x, 0.f, h, l);
            sWh[(cb + 0) * PWP + k] = *(__nv_bfloat16*)&h;
            sWl[(cb + 0) * PWP + k] = *(__nv_bfloat16*)&l;
            cvt_pair(v.y, 0.f, h, l);
            sWh[(cb + 1) * PWP + k] = *(__nv_bfloat16*)&h;
            sWl[(cb + 1) * PWP + k] = *(__nv_bfloat16*)&l;
            cvt_pair(v.z, 0.f, h, l);
            sWh[(cb + 2) * PWP + k] = *(__nv_bfloat16*)&h;
            sWl[(cb + 2) * PWP + k] = *(__nv_bfloat16*)&l;
            cvt_pair(v.w, 0.f, h, l);
            sWh[(cb + 3) * PWP + k] = *(__nv_bfloat16*)&h;
            sWl[(cb + 3) * PWP + k] = *(__nv_bfloat16*)&l;
        }
    }
    __syncthreads();

    // ---- A fragments: warp w owns rows w*16..+15, k = 0..63 ---------------
    unsigned ah[4][4], al[4][4];
    {
        unsigned xa = smem_u32(sXh) + (w * 16 + (lane & 15)) * (PWP * 2) + (lane >> 4) * 16;
        unsigned xb = smem_u32(sXl) + (w * 16 + (lane & 15)) * (PWP * 2) + (lane >> 4) * 16;
#pragma unroll
        for (int ks = 0; ks < 4; ks++) {
            LDMX4(ah[ks], xa + ks * 32);
            LDMX4(al[ks], xb + ks * 32);
        }
    }

    // ---- 12 n-tiles of 8 cols; 4 k-steps x 3 passes each ------------------
    // Each B LDMX4 covers 64 bytes (= 32 k elems) per row: k32..63 is at +64B.
    float d[12][4];
#pragma unroll
    for (int nt = 0; nt < 12; nt++) {
        d[nt][0] = d[nt][1] = d[nt][2] = d[nt][3] = 0.f;
        unsigned wbh = smem_u32(sWh) + (nt * 8 + (lane & 7)) * (PWP * 2) + (lane >> 3) * 16;
        unsigned wbl = smem_u32(sWl) + (nt * 8 + (lane & 7)) * (PWP * 2) + (lane >> 3) * 16;
        unsigned bh0[4], bh1[4], bl0[4], bl1[4];
        LDMX4(bh0, wbh);          // k 0..31
        LDMX4(bh1, wbh + 64);     // k 32..63
        LDMX4(bl0, wbl);
        LDMX4(bl1, wbl + 64);
        // hi*hi
        mma16816(d[nt], ah[0], bh0 + 0);
        mma16816(d[nt], ah[1], bh0 + 2);
        mma16816(d[nt], ah[2], bh1 + 0);
        mma16816(d[nt], ah[3], bh1 + 2);
        // lo*hi
        mma16816(d[nt], al[0], bh0 + 0);
        mma16816(d[nt], al[1], bh0 + 2);
        mma16816(d[nt], al[2], bh1 + 0);
        mma16816(d[nt], al[3], bh1 + 2);
        // hi*lo
        mma16816(d[nt], ah[0], bl0 + 0);
        mma16816(d[nt], ah[1], bl0 + 2);
        mma16816(d[nt], ah[2], bl1 + 0);
        mma16816(d[nt], ah[3], bl1 + 2);
    }

    // ---- Epilogue: add bias, split, store packed hi/lo --------------------
    {
        int r0 = row0 + w * 16 + (lane >> 2);
        int r1 = r0 + 8;
        __nv_bfloat16* dh[3] = {g_fh, g_gh, g_hh};
        __nv_bfloat16* dl[3] = {g_fl, g_gl, g_hl};
        const float* bias[3] = {bf, bg, bh};
#pragma unroll
        for (int nt = 0; nt < 12; nt++) {
            const int p  = nt >> 2;                       // projection id
            int c  = (nt & 3) * 8 + (lane & 3) * 2;       // col within proj [0,32)
            float b0 = bias[p][c], b1 = bias[p][c + 1];
            unsigned hi, lo;
            cvt_pair(d[nt][0] + b0, d[nt][1] + b1, hi, lo);
            *(unsigned*)(dh[p] + (size_t)r0 * CB + c) = hi;
            *(unsigned*)(dl[p] + (size_t)r0 * CB + c) = lo;
            cvt_pair(d[nt][2] + b0, d[nt][3] + b1, hi, lo);
            *(unsigned*)(dh[p] + (size_t)r1 * CB + c) = hi;
            *(unsigned*)(dl[p] + (size_t)r1 * CB + c) = lo;
        }
    }
}

// ---------------------------------------------------------------------------
// Kernel 2: flash attention, mma.sync bf16 3-pass split, cp.async double-buffer
// ---------------------------------------------------------------------------
__global__ __launch_bounds__(256, 1) void attn_kernel()
{
    extern __shared__ __align__(16) unsigned char smem[];
    const unsigned sbase = smem_u32(smem);

    const int b  = blockIdx.y;
    const int q0 = blockIdx.x * QT;
    const int k0 = blockIdx.z * (NTOK / SPLITS);
    const int t  = threadIdx.x;
    const int w  = t >> 5;
    const int lane = t & 31;

    const int qrow = t >> 1, qhalf = t & 1;
    const int krow = t >> 2, kq = t & 3;
    const size_t qoff = (size_t)(b * NTOK + q0 + qrow) * CB + qhalf * 16;
    const unsigned qdH = sbase + OFF_QH + qrow * KPB + qhalf * 32;
    const unsigned qdL = sbase + OFF_QL + qrow * KPB + qhalf * 32;

    cp16(qdH,      g_gh + qoff);
    cp16(qdH + 16, g_gh + qoff + 8);
    cp16(qdL,      g_gl + qoff);
    cp16(qdL + 16, g_gl + qoff + 8);
    {
        size_t goff = (size_t)(b * NTOK + k0 + krow) * CB + kq * 8;
        unsigned so = sbase + OFF_BUF + krow * KPB + kq * 16;
        cp16(so + BKH, g_fh + goff);
        cp16(so + BKL, g_fl + goff);
        cp16(so + BVH, g_hh + goff);
        cp16(so + BVL, g_hl + goff);
    }
    CP_COMMIT();
    {
        size_t goff = (size_t)(b * NTOK + k0 + KTILE + krow) * CB + kq * 8;
        unsigned so = sbase + OFF_BUF + BUF_SZ + krow * KPB + kq * 16;
        cp16(so + BKH, g_fh + goff);
        cp16(so + BKL, g_fl + goff);
        cp16(so + BVH, g_hh + goff);
        cp16(so + BVL, g_hl + goff);
    }
    CP_COMMIT();

    unsigned qh[2][4], ql[2][4];
    float m0 = -1e30f, m1 = -1e30f, l0 = 0.f, l1 = 0.f;
    float o[4][4];
#pragma unroll
    for (int nn = 0; nn < 4; nn++)
#pragma unroll
        for (int j = 0; j < 4; j++) o[nn][j] = 0.f;

    for (int kt = 0; kt < KTILES; kt++) {
        CP_WAIT1();
        __syncthreads();

        if (kt == 0) {
            unsigned qa = sbase + OFF_QH + (w * 16 + (lane & 15)) * KPB + (lane >> 4) * 16;
            unsigned qb = sbase + OFF_QL + (w * 16 + (lane & 15)) * KPB + (lane >> 4) * 16;
            LDMX4(qh[0], qa);
            LDMX4(qh[1], qa + 32);
            LDMX4(ql[0], qb);
            LDMX4(ql[1], qb + 32);
        }

        const unsigned bufb = sbase + OFF_BUF + (kt & 1) * BUF_SZ;
        const unsigned kaddr_h = bufb + BKH + (lane & 7) * KPB + (lane >> 3) * 16;
        const unsigned kaddr_l = bufb + BKL + (lane & 7) * KPB + (lane >> 3) * 16;
        const unsigned vbase_h = bufb + BVH + lane * KPB;
        const unsigned vbase_l = bufb + BVL + lane * KPB;

        float s[8][4];
#pragma unroll
        for (int n = 0; n < 8; n++) {
            s[n][0] = s[n][1] = s[n][2] = s[n][3] = 0.f;
            unsigned kh[4], kl[4];
            LDMX4(kh, kaddr_h + n * 8 * KPB);
            LDMX4(kl, kaddr_l + n * 8 * KPB);
            mma16816(s[n], qh[0], kh + 0);
            mma16816(s[n], qh[1], kh + 2);
            mma16816(s[n], ql[0], kh + 0);
            mma16816(s[n], ql[1], kh + 2);
            mma16816(s[n], qh[0], kl + 0);
            mma16816(s[n], qh[1], kl + 2);
        }

        float r0 = -1e30f, r1 = -1e30f;
#pragma unroll
        for (int n = 0; n < 8; n++) {
            r0 = fmaxf(r0, fmaxf(s[n][0], s[n][1]));
            r1 = fmaxf(r1, fmaxf(s[n][2], s[n][3]));
        }
        r0 = fmaxf(r0, __shfl_xor_sync(0xffffffffu, r0, 1));
        r0 = fmaxf(r0, __shfl_xor_sync(0xffffffffu, r0, 2));
        r1 = fmaxf(r1, __shfl_xor_sync(0xffffffffu, r1, 1));
        r1 = fmaxf(r1, __shfl_xor_sync(0xffffffffu, r1, 2));
        float mn0 = fmaxf(m0, r0), mn1 = fmaxf(m1, r1);
        float al0 = __expf(m0 - mn0), al1 = __expf(m1 - mn1);

        float ps0 = 0.f, ps1 = 0.f;
        unsigned ph[4][4], pl[4][4];
#pragma unroll
        for (int n = 0; n < 8; n++) {
            float p0 = __expf(s[n][0] - mn0);
            float p1 = __expf(s[n][1] - mn0);
            float p2 = __expf(s[n][2] - mn1);
            float p3 = __expf(s[n][3] - mn1);
            ps0 += p0 + p1;  ps1 += p2 + p3;
            int kk = n >> 1, hset = (n & 1) * 2;
            cvt_pair(p0, p1, ph[kk][hset + 0], pl[kk][hset + 0]);
            cvt_pair(p2, p3, ph[kk][hset + 1], pl[kk][hset + 1]);
        }
        ps0 += __shfl_xor_sync(0xffffffffu, ps0, 1);
        ps0 += __shfl_xor_sync(0xffffffffu, ps0, 2);
        ps1 += __shfl_xor_sync(0xffffffffu, ps1, 1);
        ps1 += __shfl_xor_sync(0xffffffffu, ps1, 2);
        l0 = l0 * al0 + ps0;  l1 = l1 * al1 + ps1;
        m0 = mn0;  m1 = mn1;

#pragma unroll
        for (int nn = 0; nn < 4; nn++) {
            o[nn][0] *= al0; o[nn][1] *= al0;
            o[nn][2] *= al1; o[nn][3] *= al1;
        }

#pragma unroll
        for (int kkp = 0; kkp < 2; kkp++) {
            int kk0 = kkp * 2, kk1 = kkp * 2 + 1;
#pragma unroll
            for (int nn = 0; nn < 4; nn++) {
                unsigned vh[4], vl[4];
                unsigned off = (unsigned)(kkp * 32 * KPB + nn * 16);
                LDMX4T(vh, vbase_h + off);
                LDMX4T(vl, vbase_l + off);
                mma16816(o[nn], ph[kk0], vh + 0);
                mma16816(o[nn], ph[kk1], vh + 2);
                mma16816(o[nn], pl[kk0], vh + 0);
                mma16816(o[nn], pl[kk1], vh + 2);
                mma16816(o[nn], ph[kk0], vl + 0);
                mma16816(o[nn], ph[kk1], vl + 2);
            }
        }

        __syncthreads();
        if (kt + 2 < KTILES) {
            size_t goff = (size_t)(b * NTOK + k0 + (kt + 2) * KTILE + krow) * CB + kq * 8;
            unsigned so = bufb + krow * KPB + kq * 16;
            cp16(so + BKH, g_fh + goff);
            cp16(so + BKL, g_fl + goff);
            cp16(so + BVH, g_hh + goff);
            cp16(so + BVL, g_hl + goff);
        }
        CP_COMMIT();
    }

    {
        int z = blockIdx.z;
        int r = lane >> 2;
        int c = (lane & 3) * 2;
        int grow0 = b * NTOK + q0 + w * 16 + r;
        int grow1 = grow0 + 8;
        if ((lane & 3) == 0) {
            g_m[z][grow0] = m0;  g_l[z][grow0] = l0;
            g_m[z][grow1] = m1;  g_l[z][grow1] = l1;
        }
#pragma unroll
        for (int nn = 0; nn < 4; nn++) {
            *(float2*)&g_part[z][(size_t)grow0 * CB + nn * 8 + c] = make_float2(o[nn][0], o[nn][1]);
            *(float2*)&g_part[z][(size_t)grow1 * CB + nn * 8 + c] = make_float2(o[nn][2], o[nn][3]);
        }
    }
}

// ---------------------------------------------------------------------------
// Kernel 3: fused combine + output projection + residual
// ---------------------------------------------------------------------------
__global__ __launch_bounds__(256) void outc_kernel(
    const float* __restrict__ x,
    const float* __restrict__ Wo, const float* __restrict__ bo,
    const float* __restrict__ gamma,
    float* __restrict__ out)
{
    int idx = blockIdx.x * blockDim.x + threadIdx.x;   // [0, B*N*32)
    int row = idx >> 5;
    int sub = idx & 31;
    int c4  = (sub & 15) * 4;
    int kh  = sub >> 4;

    float m0 = g_m[0][row], m1 = g_m[1][row];
    float l0 = g_l[0][row], l1 = g_l[1][row];
    float M  = fmaxf(m0, m1);
    float w0 = __expf(m0 - M), w1 = __expf(m1 - M);
    float inv = 1.0f / (l0 * w0 + l1 * w1);
    w0 *= inv;  w1 *= inv;

    const float4* p0r = (const float4*)(&g_part[0][0] + (size_t)row * CB + kh * 16);
    const float4* p1r = (const float4*)(&g_part[1][0] + (size_t)row * CB + kh * 16);

    float4 o = make_float4(0.f, 0.f, 0.f, 0.f);
#pragma unroll
    for (int j4 = 0; j4 < 4; j4++) {
        float4 a = p0r[j4], bb = p1r[j4];
        float bs[4] = {a.x * w0 + bb.x * w1, a.y * w0 + bb.y * w1,
                       a.z * w0 + bb.z * w1, a.w * w0 + bb.w * w1};
#pragma unroll
        for (int j = 0; j < 4; j++) {
            float4 wv = *(const float4*)(Wo + (kh * 16 + j4 * 4 + j) * CIN + c4);
            o.x = fmaf(bs[j], wv.x, o.x);
            o.y = fmaf(bs[j], wv.y, o.y);
            o.z = fmaf(bs[j], wv.z, o.z);
            o.w = fmaf(bs[j], wv.w, o.w);
        }
    }
    o.x += __shfl_xor_sync(0xffffffffu, o.x, 16);
    o.y += __shfl_xor_sync(0xffffffffu, o.y, 16);
    o.z += __shfl_xor_sync(0xffffffffu, o.z, 16);
    o.w += __shfl_xor_sync(0xffffffffu, o.w, 16);

    if (kh == 0) {
        float gm = gamma[0];
        float4 bv = *(const float4*)(bo + c4);
        float4 xv = *(const float4*)(x + (size_t)row * CIN + c4);
        float4 r;
        r.x = xv.x + gm * (o.x + bv.x);
        r.y = xv.y + gm * (o.y + bv.y);
        r.z = xv.z + gm * (o.z + bv.z);
        r.w = xv.w + gm * (o.w + bv.w);
        *(float4*)(out + (size_t)row * CIN + c4) = r;
    }
}

// ---------------------------------------------------------------------------
extern "C" void kernel_launch(void* const* d_in, const int* in_sizes, int n_in,
                              void* d_out, int out_size)
{
    const float* x     = (const float*)d_in[0];
    const float* Wf    = (const float*)d_in[1];
    const float* bf    = (const float*)d_in[2];
    const float* Wg    = (const float*)d_in[3];
    const float* bg    = (const float*)d_in[4];
    const float* Wh    = (const float*)d_in[5];
    const float* bh    = (const float*)d_in[6];
    const float* Wo    = (const float*)d_in[7];
    const float* bo    = (const float*)d_in[8];
    const float* gamma = (const float*)d_in[9];
    float* out = (float*)d_out;
    (void)in_sizes; (void)n_in; (void)out_size;

    cudaFuncSetAttribute(attn_kernel,
                         cudaFuncAttributeMaxDynamicSharedMemorySize, SMEM_BYTES);

    proj_mma_kernel<<<BATCH * NTOK / PROWS, 128>>>(x, Wf, bf, Wg, bg, Wh, bh);

    dim3 agrid(NTOK / QT, BATCH, SPLITS);
    attn_kernel<<<agrid, 256, SMEM_BYTES>>>();

    outc_kernel<<<BATCH * NTOK * 32 / 256, 256>>>(x, Wo, bo, gamma, out);
}

// round 7
// speedup vs baseline: 1.1652x; 1.0330x over previous
#include <cuda_runtime.h>
#include <cuda_bf16.h>

// ---------------------------------------------------------------------------
// Problem constants
// ---------------------------------------------------------------------------
#define NTOK 4096
#define CB   32
#define CIN  64
#define BATCH 2

#define QT     128                     // queries per block (8 warps x 16 rows)
#define KTILE  64                      // keys per tile
#define SPLITS 4
#define KTILES (NTOK / SPLITS / KTILE) // 16
#define KP     40                      // padded row stride (bf16 elems)
#define KPB    80                      // padded row stride bytes

// attn dynamic SMEM layout (bytes)
#define OFF_QH   0
#define OFF_QL   10240
#define OFF_BUF  20480
#define BUF_SZ   20480
#define BKH      0
#define BKL      5120
#define BVH      10240
#define BVL      15360
#define SMEM_BYTES (OFF_BUF + 2 * BUF_SZ)   // 61440 (x2 blocks/SM = 120KB)

// proj tiling
#define PROWS 64                       // rows per proj block
#define PWP   72                       // padded row stride (bf16) = 144B
#define NPROJ 96                       // 3 * 32 output cols

// ---------------------------------------------------------------------------
// Scratch (no cudaMalloc allowed)
// ---------------------------------------------------------------------------
__device__ __align__(16) __nv_bfloat16 g_gh[BATCH * NTOK * CB];
__device__ __align__(16) __nv_bfloat16 g_gl[BATCH * NTOK * CB];
__device__ __align__(16) __nv_bfloat16 g_fh[BATCH * NTOK * CB];
__device__ __align__(16) __nv_bfloat16 g_fl[BATCH * NTOK * CB];
__device__ __align__(16) __nv_bfloat16 g_hh[BATCH * NTOK * CB];
__device__ __align__(16) __nv_bfloat16 g_hl[BATCH * NTOK * CB];
__device__ __align__(16) float g_part[SPLITS][BATCH * NTOK * CB];
__device__ __align__(16) float g_m[SPLITS][BATCH * NTOK];
__device__ __align__(16) float g_l[SPLITS][BATCH * NTOK];

// ---------------------------------------------------------------------------
// Helpers
// ---------------------------------------------------------------------------
__device__ __forceinline__ unsigned smem_u32(const void* p) {
    unsigned a;
    asm("{ .reg .u64 t; cvta.to.shared.u64 t, %1; cvt.u32.u64 %0, t; }"
        : "=r"(a) : "l"(p));
    return a;
}
__device__ __forceinline__ void cp16(unsigned dst, const void* src) {
    asm volatile("cp.async.cg.shared.global [%0], [%1], 16;"
                 :: "r"(dst), "l"(src) : "memory");
}
#define CP_COMMIT() asm volatile("cp.async.commit_group;" ::: "memory")
#define CP_WAIT1()  asm volatile("cp.async.wait_group 1;" ::: "memory")

#define LDMX4(r, a) \
    asm volatile("ldmatrix.sync.aligned.m8n8.x4.shared.b16 {%0,%1,%2,%3}, [%4];" \
        : "=r"((r)[0]), "=r"((r)[1]), "=r"((r)[2]), "=r"((r)[3]) : "r"(a))
#define LDMX4T(r, a) \
    asm volatile("ldmatrix.sync.aligned.m8n8.x4.trans.shared.b16 {%0,%1,%2,%3}, [%4];" \
        : "=r"((r)[0]), "=r"((r)[1]), "=r"((r)[2]), "=r"((r)[3]) : "r"(a))

__device__ __forceinline__ void mma16816(float* d, const unsigned* a, const unsigned* b) {
    asm volatile(
        "mma.sync.aligned.m16n8k16.row.col.f32.bf16.bf16.f32 "
        "{%0,%1,%2,%3}, {%4,%5,%6,%7}, {%8,%9}, {%0,%1,%2,%3};"
        : "+f"(d[0]), "+f"(d[1]), "+f"(d[2]), "+f"(d[3])
        : "r"(a[0]), "r"(a[1]), "r"(a[2]), "r"(a[3]), "r"(b[0]), "r"(b[1]));
}

__device__ __forceinline__ void cvt_pair(float f0, float f1, unsigned& hi, unsigned& lo) {
    __nv_bfloat162 h = __floats2bfloat162_rn(f0, f1);
    float r0 = f0 - __bfloat162float(h.x);
    float r1 = f1 - __bfloat162float(h.y);
    __nv_bfloat162 l = __floats2bfloat162_rn(r0, r1);
    hi = *(unsigned*)&h;
    lo = *(unsigned*)&l;
}

// ---------------------------------------------------------------------------
// Kernel 1: projections as one HMMA GEMM (unchanged from R6 — passing)
// ---------------------------------------------------------------------------
__global__ __launch_bounds__(128) void proj_mma_kernel(
    const float* __restrict__ x,
    const float* __restrict__ Wf, const float* __restrict__ bf,
    const float* __restrict__ Wg, const float* __restrict__ bg,
    const float* __restrict__ Wh, const float* __restrict__ bh)
{
    __shared__ __nv_bfloat16 sXh[PROWS * PWP], sXl[PROWS * PWP];
    __shared__ __nv_bfloat16 sWh[NPROJ * PWP], sWl[NPROJ * PWP];

    const int t    = threadIdx.x;
    const int w    = t >> 5;
    const int lane = t & 31;
    const int row0 = blockIdx.x * PROWS;

    {
        int r = t >> 1, half = t & 1;
        const float4* src = (const float4*)(x + (size_t)(row0 + r) * CIN + half * 32);
        int e = r * PWP + half * 32;
#pragma unroll
        for (int i = 0; i < 8; i++) {
            float4 v = src[i];
            unsigned h0, l0, h1, l1;
            cvt_pair(v.x, v.y, h0, l0);
            cvt_pair(v.z, v.w, h1, l1);
            *(uint2*)(sXh + e + i * 4) = make_uint2(h0, h1);
            *(uint2*)(sXl + e + i * 4) = make_uint2(l0, l1);
        }
    }

    {
        const float* Ws[3] = {Wf, Wg, Wh};
#pragma unroll
        for (int it = 0; it < 12; it++) {
            int i = t + it * 128;
            int p = i >> 9;
            int rr = i & 511;
            int k = rr >> 3;
            int c = (rr & 7) * 4;
            float4 v = *(const float4*)(Ws[p] + k * CB + c);
            int cb = p * CB + c;
            unsigned h, l;
            cvt_pair(v.x, 0.f, h, l);
            sWh[(cb + 0) * PWP + k] = *(__nv_bfloat16*)&h;
            sWl[(cb + 0) * PWP + k] = *(__nv_bfloat16*)&l;
            cvt_pair(v.y, 0.f, h, l);
            sWh[(cb + 1) * PWP + k] = *(__nv_bfloat16*)&h;
            sWl[(cb + 1) * PWP + k] = *(__nv_bfloat16*)&l;
            cvt_pair(v.z, 0.f, h, l);
            sWh[(cb + 2) * PWP + k] = *(__nv_bfloat16*)&h;
            sWl[(cb + 2) * PWP + k] = *(__nv_bfloat16*)&l;
            cvt_pair(v.w, 0.f, h, l);
            sWh[(cb + 3) * PWP + k] = *(__nv_bfloat16*)&h;
            sWl[(cb + 3) * PWP + k] = *(__nv_bfloat16*)&l;
        }
    }
    __syncthreads();

    unsigned ah[4][4], al[4][4];
    {
        unsigned xa = smem_u32(sXh) + (w * 16 + (lane & 15)) * (PWP * 2) + (lane >> 4) * 16;
        unsigned xb = smem_u32(sXl) + (w * 16 + (lane & 15)) * (PWP * 2) + (lane >> 4) * 16;
#pragma unroll
        for (int ks = 0; ks < 4; ks++) {
            LDMX4(ah[ks], xa + ks * 32);
            LDMX4(al[ks], xb + ks * 32);
        }
    }

    float d[12][4];
#pragma unroll
    for (int nt = 0; nt < 12; nt++) {
        d[nt][0] = d[nt][1] = d[nt][2] = d[nt][3] = 0.f;
        unsigned wbh = smem_u32(sWh) + (nt * 8 + (lane & 7)) * (PWP * 2) + (lane >> 3) * 16;
        unsigned wbl = smem_u32(sWl) + (nt * 8 + (lane & 7)) * (PWP * 2) + (lane >> 3) * 16;
        unsigned bh0[4], bh1[4], bl0[4], bl1[4];
        LDMX4(bh0, wbh);
        LDMX4(bh1, wbh + 64);
        LDMX4(bl0, wbl);
        LDMX4(bl1, wbl + 64);
        mma16816(d[nt], ah[0], bh0 + 0);
        mma16816(d[nt], ah[1], bh0 + 2);
        mma16816(d[nt], ah[2], bh1 + 0);
        mma16816(d[nt], ah[3], bh1 + 2);
        mma16816(d[nt], al[0], bh0 + 0);
        mma16816(d[nt], al[1], bh0 + 2);
        mma16816(d[nt], al[2], bh1 + 0);
        mma16816(d[nt], al[3], bh1 + 2);
        mma16816(d[nt], ah[0], bl0 + 0);
        mma16816(d[nt], ah[1], bl0 + 2);
        mma16816(d[nt], ah[2], bl1 + 0);
        mma16816(d[nt], ah[3], bl1 + 2);
    }

    {
        int r0 = row0 + w * 16 + (lane >> 2);
        int r1 = r0 + 8;
        __nv_bfloat16* dh[3] = {g_fh, g_gh, g_hh};
        __nv_bfloat16* dl[3] = {g_fl, g_gl, g_hl};
        const float* bias[3] = {bf, bg, bh};
#pragma unroll
        for (int nt = 0; nt < 12; nt++) {
            const int p  = nt >> 2;
            int c  = (nt & 3) * 8 + (lane & 3) * 2;
            float b0 = bias[p][c], b1 = bias[p][c + 1];
            unsigned hi, lo;
            cvt_pair(d[nt][0] + b0, d[nt][1] + b1, hi, lo);
            *(unsigned*)(dh[p] + (size_t)r0 * CB + c) = hi;
            *(unsigned*)(dl[p] + (size_t)r0 * CB + c) = lo;
            cvt_pair(d[nt][2] + b0, d[nt][3] + b1, hi, lo);
            *(unsigned*)(dh[p] + (size_t)r1 * CB + c) = hi;
            *(unsigned*)(dl[p] + (size_t)r1 * CB + c) = lo;
        }
    }
}

// ---------------------------------------------------------------------------
// Kernel 2: flash attention — SPLITS=4, 2 blocks/SM for latency hiding
// ---------------------------------------------------------------------------
__global__ __launch_bounds__(256, 2) void attn_kernel()
{
    extern __shared__ __align__(16) unsigned char smem[];
    const unsigned sbase = smem_u32(smem);

    const int b  = blockIdx.y;
    const int q0 = blockIdx.x * QT;
    const int k0 = blockIdx.z * (NTOK / SPLITS);
    const int t  = threadIdx.x;
    const int w  = t >> 5;
    const int lane = t & 31;

    const int qrow = t >> 1, qhalf = t & 1;
    const int krow = t >> 2, kq = t & 3;
    const size_t qoff = (size_t)(b * NTOK + q0 + qrow) * CB + qhalf * 16;
    const unsigned qdH = sbase + OFF_QH + qrow * KPB + qhalf * 32;
    const unsigned qdL = sbase + OFF_QL + qrow * KPB + qhalf * 32;

    cp16(qdH,      g_gh + qoff);
    cp16(qdH + 16, g_gh + qoff + 8);
    cp16(qdL,      g_gl + qoff);
    cp16(qdL + 16, g_gl + qoff + 8);
    {
        size_t goff = (size_t)(b * NTOK + k0 + krow) * CB + kq * 8;
        unsigned so = sbase + OFF_BUF + krow * KPB + kq * 16;
        cp16(so + BKH, g_fh + goff);
        cp16(so + BKL, g_fl + goff);
        cp16(so + BVH, g_hh + goff);
        cp16(so + BVL, g_hl + goff);
    }
    CP_COMMIT();
    {
        size_t goff = (size_t)(b * NTOK + k0 + KTILE + krow) * CB + kq * 8;
        unsigned so = sbase + OFF_BUF + BUF_SZ + krow * KPB + kq * 16;
        cp16(so + BKH, g_fh + goff);
        cp16(so + BKL, g_fl + goff);
        cp16(so + BVH, g_hh + goff);
        cp16(so + BVL, g_hl + goff);
    }
    CP_COMMIT();

    unsigned qh[2][4], ql[2][4];
    float m0 = -1e30f, m1 = -1e30f, l0 = 0.f, l1 = 0.f;
    float o[4][4];
#pragma unroll
    for (int nn = 0; nn < 4; nn++)
#pragma unroll
        for (int j = 0; j < 4; j++) o[nn][j] = 0.f;

    for (int kt = 0; kt < KTILES; kt++) {
        CP_WAIT1();
        __syncthreads();

        if (kt == 0) {
            unsigned qa = sbase + OFF_QH + (w * 16 + (lane & 15)) * KPB + (lane >> 4) * 16;
            unsigned qb = sbase + OFF_QL + (w * 16 + (lane & 15)) * KPB + (lane >> 4) * 16;
            LDMX4(qh[0], qa);
            LDMX4(qh[1], qa + 32);
            LDMX4(ql[0], qb);
            LDMX4(ql[1], qb + 32);
        }

        const unsigned bufb = sbase + OFF_BUF + (kt & 1) * BUF_SZ;
        const unsigned kaddr_h = bufb + BKH + (lane & 7) * KPB + (lane >> 3) * 16;
        const unsigned kaddr_l = bufb + BKL + (lane & 7) * KPB + (lane >> 3) * 16;
        const unsigned vbase_h = bufb + BVH + lane * KPB;
        const unsigned vbase_l = bufb + BVL + lane * KPB;

        float s[8][4];
#pragma unroll
        for (int n = 0; n < 8; n++) {
            s[n][0] = s[n][1] = s[n][2] = s[n][3] = 0.f;
            unsigned kh[4], kl[4];
            LDMX4(kh, kaddr_h + n * 8 * KPB);
            LDMX4(kl, kaddr_l + n * 8 * KPB);
            mma16816(s[n], qh[0], kh + 0);
            mma16816(s[n], qh[1], kh + 2);
            mma16816(s[n], ql[0], kh + 0);
            mma16816(s[n], ql[1], kh + 2);
            mma16816(s[n], qh[0], kl + 0);
            mma16816(s[n], qh[1], kl + 2);
        }

        float r0 = -1e30f, r1 = -1e30f;
#pragma unroll
        for (int n = 0; n < 8; n++) {
            r0 = fmaxf(r0, fmaxf(s[n][0], s[n][1]));
            r1 = fmaxf(r1, fmaxf(s[n][2], s[n][3]));
        }
        r0 = fmaxf(r0, __shfl_xor_sync(0xffffffffu, r0, 1));
        r0 = fmaxf(r0, __shfl_xor_sync(0xffffffffu, r0, 2));
        r1 = fmaxf(r1, __shfl_xor_sync(0xffffffffu, r1, 1));
        r1 = fmaxf(r1, __shfl_xor_sync(0xffffffffu, r1, 2));
        float mn0 = fmaxf(m0, r0), mn1 = fmaxf(m1, r1);
        float al0 = __expf(m0 - mn0), al1 = __expf(m1 - mn1);

        float ps0 = 0.f, ps1 = 0.f;
        unsigned ph[4][4], pl[4][4];
#pragma unroll
        for (int n = 0; n < 8; n++) {
            float p0 = __expf(s[n][0] - mn0);
            float p1 = __expf(s[n][1] - mn0);
            float p2 = __expf(s[n][2] - mn1);
            float p3 = __expf(s[n][3] - mn1);
            ps0 += p0 + p1;  ps1 += p2 + p3;
            int kk = n >> 1, hset = (n & 1) * 2;
            cvt_pair(p0, p1, ph[kk][hset + 0], pl[kk][hset + 0]);
            cvt_pair(p2, p3, ph[kk][hset + 1], pl[kk][hset + 1]);
        }
        ps0 += __shfl_xor_sync(0xffffffffu, ps0, 1);
        ps0 += __shfl_xor_sync(0xffffffffu, ps0, 2);
        ps1 += __shfl_xor_sync(0xffffffffu, ps1, 1);
        ps1 += __shfl_xor_sync(0xffffffffu, ps1, 2);
        l0 = l0 * al0 + ps0;  l1 = l1 * al1 + ps1;
        m0 = mn0;  m1 = mn1;

#pragma unroll
        for (int nn = 0; nn < 4; nn++) {
            o[nn][0] *= al0; o[nn][1] *= al0;
            o[nn][2] *= al1; o[nn][3] *= al1;
        }

#pragma unroll
        for (int kkp = 0; kkp < 2; kkp++) {
            int kk0 = kkp * 2, kk1 = kkp * 2 + 1;
#pragma unroll
            for (int nn = 0; nn < 4; nn++) {
                unsigned vh[4], vl[4];
                unsigned off = (unsigned)(kkp * 32 * KPB + nn * 16);
                LDMX4T(vh, vbase_h + off);
                LDMX4T(vl, vbase_l + off);
                mma16816(o[nn], ph[kk0], vh + 0);
                mma16816(o[nn], ph[kk1], vh + 2);
                mma16816(o[nn], pl[kk0], vh + 0);
                mma16816(o[nn], pl[kk1], vh + 2);
                mma16816(o[nn], ph[kk0], vl + 0);
                mma16816(o[nn], ph[kk1], vl + 2);
            }
        }

        __syncthreads();
        if (kt + 2 < KTILES) {
            size_t goff = (size_t)(b * NTOK + k0 + (kt + 2) * KTILE + krow) * CB + kq * 8;
            unsigned so = bufb + krow * KPB + kq * 16;
            cp16(so + BKH, g_fh + goff);
            cp16(so + BKL, g_fl + goff);
            cp16(so + BVH, g_hh + goff);
            cp16(so + BVL, g_hl + goff);
        }
        CP_COMMIT();
    }

    {
        int z = blockIdx.z;
        int r = lane >> 2;
        int c = (lane & 3) * 2;
        int grow0 = b * NTOK + q0 + w * 16 + r;
        int grow1 = grow0 + 8;
        if ((lane & 3) == 0) {
            g_m[z][grow0] = m0;  g_l[z][grow0] = l0;
            g_m[z][grow1] = m1;  g_l[z][grow1] = l1;
        }
#pragma unroll
        for (int nn = 0; nn < 4; nn++) {
            *(float2*)&g_part[z][(size_t)grow0 * CB + nn * 8 + c] = make_float2(o[nn][0], o[nn][1]);
            *(float2*)&g_part[z][(size_t)grow1 * CB + nn * 8 + c] = make_float2(o[nn][2], o[nn][3]);
        }
    }
}

// ---------------------------------------------------------------------------
// Kernel 3: fused combine(4 splits) + output projection + residual
// ---------------------------------------------------------------------------
__global__ __launch_bounds__(256) void outc_kernel(
    const float* __restrict__ x,
    const float* __restrict__ Wo, const float* __restrict__ bo,
    const float* __restrict__ gamma,
    float* __restrict__ out)
{
    int idx = blockIdx.x * blockDim.x + threadIdx.x;   // [0, B*N*32)
    int row = idx >> 5;
    int sub = idx & 31;
    int c4  = (sub & 15) * 4;
    int kh  = sub >> 4;

    float mz[SPLITS], lz[SPLITS];
    float M = -1e30f;
#pragma unroll
    for (int z = 0; z < SPLITS; z++) {
        mz[z] = g_m[z][row];
        lz[z] = g_l[z][row];
        M = fmaxf(M, mz[z]);
    }
    float wz[SPLITS];
    float denom = 0.f;
#pragma unroll
    for (int z = 0; z < SPLITS; z++) {
        wz[z] = __expf(mz[z] - M);
        denom += lz[z] * wz[z];
    }
    float inv = 1.0f / denom;
#pragma unroll
    for (int z = 0; z < SPLITS; z++) wz[z] *= inv;

    float4 o = make_float4(0.f, 0.f, 0.f, 0.f);
#pragma unroll
    for (int j4 = 0; j4 < 4; j4++) {
        float bs[4] = {0.f, 0.f, 0.f, 0.f};
#pragma unroll
        for (int z = 0; z < SPLITS; z++) {
            float4 a = *(const float4*)(&g_part[z][0] + (size_t)row * CB + kh * 16 + j4 * 4);
            bs[0] += a.x * wz[z];
            bs[1] += a.y * wz[z];
            bs[2] += a.z * wz[z];
            bs[3] += a.w * wz[z];
        }
#pragma unroll
        for (int j = 0; j < 4; j++) {
            float4 wv = *(const float4*)(Wo + (kh * 16 + j4 * 4 + j) * CIN + c4);
            o.x = fmaf(bs[j], wv.x, o.x);
            o.y = fmaf(bs[j], wv.y, o.y);
            o.z = fmaf(bs[j], wv.z, o.z);
            o.w = fmaf(bs[j], wv.w, o.w);
        }
    }
    o.x += __shfl_xor_sync(0xffffffffu, o.x, 16);
    o.y += __shfl_xor_sync(0xffffffffu, o.y, 16);
    o.z += __shfl_xor_sync(0xffffffffu, o.z, 16);
    o.w += __shfl_xor_sync(0xffffffffu, o.w, 16);

    if (kh == 0) {
        float gm = gamma[0];
        float4 bv = *(const float4*)(bo + c4);
        float4 xv = *(const float4*)(x + (size_t)row * CIN + c4);
        float4 r;
        r.x = xv.x + gm * (o.x + bv.x);
        r.y = xv.y + gm * (o.y + bv.y);
        r.z = xv.z + gm * (o.z + bv.z);
        r.w = xv.w + gm * (o.w + bv.w);
        *(float4*)(out + (size_t)row * CIN + c4) = r;
    }
}

// ---------------------------------------------------------------------------
extern "C" void kernel_launch(void* const* d_in, const int* in_sizes, int n_in,
                              void* d_out, int out_size)
{
    const float* x     = (const float*)d_in[0];
    const float* Wf    = (const float*)d_in[1];
    const float* bf    = (const float*)d_in[2];
    const float* Wg    = (const float*)d_in[3];
    const float* bg    = (const float*)d_in[4];
    const float* Wh    = (const float*)d_in[5];
    const float* bh    = (const float*)d_in[6];
    const float* Wo    = (const float*)d_in[7];
    const float* bo    = (const float*)d_in[8];
    const float* gamma = (const float*)d_in[9];
    float* out = (float*)d_out;
    (void)in_sizes; (void)n_in; (void)out_size;

    cudaFuncSetAttribute(attn_kernel,
                         cudaFuncAttributeMaxDynamicSharedMemorySize, SMEM_BYTES);

    proj_mma_kernel<<<BATCH * NTOK / PROWS, 128>>>(x, Wf, bf, Wg, bg, Wh, bh);

    dim3 agrid(NTOK / QT, BATCH, SPLITS);
    attn_kernel<<<agrid, 256, SMEM_BYTES>>>();

    outc_kernel<<<BATCH * NTOK * 32 / 256, 256>>>(x, Wo, bo, gamma, out);
}

// round 8
// speedup vs baseline: 1.3305x; 1.1418x over previous
#include <cuda_runtime.h>
#include <cuda_fp16.h>

// ---------------------------------------------------------------------------
// Problem constants
// ---------------------------------------------------------------------------
#define NTOK 4096
#define CB   32
#define CIN  64
#define BATCH 2

#define QT     128                     // queries per block (8 warps x 16 rows)
#define KTILE  64                      // keys per tile
#define SPLITS 4
#define KTILES (NTOK / SPLITS / KTILE) // 16
#define KP     40                      // padded row stride (fp16 elems)
#define KPB    80                      // padded row stride bytes

// attn dynamic SMEM layout (bytes)
#define OFF_QH   0
#define OFF_QL   10240
#define OFF_BUF  20480
#define BUF_SZ   20480
#define BKH      0
#define BKL      5120
#define BVH      10240
#define BVL      15360
#define SMEM_BYTES (OFF_BUF + 2 * BUF_SZ)   // 61440 (x2 blocks/SM = 120KB)

// proj tiling
#define PROWS 64
#define PWP   72                       // padded row stride (fp16) = 144B
#define NPROJ 96

// ---------------------------------------------------------------------------
// Scratch (no cudaMalloc allowed)
// ---------------------------------------------------------------------------
__device__ __align__(16) __half g_gh[BATCH * NTOK * CB];
__device__ __align__(16) __half g_gl[BATCH * NTOK * CB];
__device__ __align__(16) __half g_fh[BATCH * NTOK * CB];
__device__ __align__(16) __half g_fl[BATCH * NTOK * CB];
__device__ __align__(16) __half g_hh[BATCH * NTOK * CB];
__device__ __align__(16) __half g_hl[BATCH * NTOK * CB];
__device__ __align__(16) float g_part[SPLITS][BATCH * NTOK * CB];
__device__ __align__(16) float g_m[SPLITS][BATCH * NTOK];
__device__ __align__(16) float g_l[SPLITS][BATCH * NTOK];

// ---------------------------------------------------------------------------
// Helpers
// ---------------------------------------------------------------------------
__device__ __forceinline__ unsigned smem_u32(const void* p) {
    unsigned a;
    asm("{ .reg .u64 t; cvta.to.shared.u64 t, %1; cvt.u32.u64 %0, t; }"
        : "=r"(a) : "l"(p));
    return a;
}
__device__ __forceinline__ void cp16(unsigned dst, const void* src) {
    asm volatile("cp.async.cg.shared.global [%0], [%1], 16;"
                 :: "r"(dst), "l"(src) : "memory");
}
#define CP_COMMIT() asm volatile("cp.async.commit_group;" ::: "memory")
#define CP_WAIT1()  asm volatile("cp.async.wait_group 1;" ::: "memory")

#define LDMX4(r, a) \
    asm volatile("ldmatrix.sync.aligned.m8n8.x4.shared.b16 {%0,%1,%2,%3}, [%4];" \
        : "=r"((r)[0]), "=r"((r)[1]), "=r"((r)[2]), "=r"((r)[3]) : "r"(a))
#define LDMX4T(r, a) \
    asm volatile("ldmatrix.sync.aligned.m8n8.x4.trans.shared.b16 {%0,%1,%2,%3}, [%4];" \
        : "=r"((r)[0]), "=r"((r)[1]), "=r"((r)[2]), "=r"((r)[3]) : "r"(a))

__device__ __forceinline__ void mma16816(float* d, const unsigned* a, const unsigned* b) {
    asm volatile(
        "mma.sync.aligned.m16n8k16.row.col.f32.f16.f16.f32 "
        "{%0,%1,%2,%3}, {%4,%5,%6,%7}, {%8,%9}, {%0,%1,%2,%3};"
        : "+f"(d[0]), "+f"(d[1]), "+f"(d[2]), "+f"(d[3])
        : "r"(a[0]), "r"(a[1]), "r"(a[2]), "r"(a[3]), "r"(b[0]), "r"(b[1]));
}

// fp32 pair -> packed fp16 hi + packed fp16 residual
__device__ __forceinline__ void cvt_pair(float f0, float f1, unsigned& hi, unsigned& lo) {
    __half2 h = __floats2half2_rn(f0, f1);
    float r0 = f0 - __low2float(h);
    float r1 = f1 - __high2float(h);
    __half2 l = __floats2half2_rn(r0, r1);
    hi = *(unsigned*)&h;
    lo = *(unsigned*)&l;
}
// fp32 -> fp16 hi + fp16 residual (scalar)
__device__ __forceinline__ void cvt1(float f, __half& h, __half& l) {
    h = __float2half_rn(f);
    l = __float2half_rn(f - __half2float(h));
}

// ---------------------------------------------------------------------------
// Kernel 1: projections as one HMMA GEMM: [B*N x 64] @ [64 x 96] + bias
// ---------------------------------------------------------------------------
__global__ __launch_bounds__(128) void proj_mma_kernel(
    const float* __restrict__ x,
    const float* __restrict__ Wf, const float* __restrict__ bf,
    const float* __restrict__ Wg, const float* __restrict__ bg,
    const float* __restrict__ Wh, const float* __restrict__ bh)
{
    __shared__ __half sXh[PROWS * PWP], sXl[PROWS * PWP];
    __shared__ __half sWh[NPROJ * PWP], sWl[NPROJ * PWP];

    const int t    = threadIdx.x;
    const int w    = t >> 5;
    const int lane = t & 31;
    const int row0 = blockIdx.x * PROWS;

    {
        int r = t >> 1, half = t & 1;
        const float4* src = (const float4*)(x + (size_t)(row0 + r) * CIN + half * 32);
        int e = r * PWP + half * 32;
#pragma unroll
        for (int i = 0; i < 8; i++) {
            float4 v = src[i];
            unsigned h0, l0, h1, l1;
            cvt_pair(v.x, v.y, h0, l0);
            cvt_pair(v.z, v.w, h1, l1);
            *(uint2*)(sXh + e + i * 4) = make_uint2(h0, h1);
            *(uint2*)(sXl + e + i * 4) = make_uint2(l0, l1);
        }
    }

    {
        const float* Ws[3] = {Wf, Wg, Wh};
#pragma unroll
        for (int it = 0; it < 12; it++) {
            int i = t + it * 128;
            int p = i >> 9;
            int rr = i & 511;
            int k = rr >> 3;
            int c = (rr & 7) * 4;
            float4 v = *(const float4*)(Ws[p] + k * CB + c);
            int cb = p * CB + c;
            __half h, l;
            cvt1(v.x, h, l);
            sWh[(cb + 0) * PWP + k] = h;  sWl[(cb + 0) * PWP + k] = l;
            cvt1(v.y, h, l);
            sWh[(cb + 1) * PWP + k] = h;  sWl[(cb + 1) * PWP + k] = l;
            cvt1(v.z, h, l);
            sWh[(cb + 2) * PWP + k] = h;  sWl[(cb + 2) * PWP + k] = l;
            cvt1(v.w, h, l);
            sWh[(cb + 3) * PWP + k] = h;  sWl[(cb + 3) * PWP + k] = l;
        }
    }
    __syncthreads();

    unsigned ah[4][4], al[4][4];
    {
        unsigned xa = smem_u32(sXh) + (w * 16 + (lane & 15)) * (PWP * 2) + (lane >> 4) * 16;
        unsigned xb = smem_u32(sXl) + (w * 16 + (lane & 15)) * (PWP * 2) + (lane >> 4) * 16;
#pragma unroll
        for (int ks = 0; ks < 4; ks++) {
            LDMX4(ah[ks], xa + ks * 32);
            LDMX4(al[ks], xb + ks * 32);
        }
    }

    float d[12][4];
#pragma unroll
    for (int nt = 0; nt < 12; nt++) {
        d[nt][0] = d[nt][1] = d[nt][2] = d[nt][3] = 0.f;
        unsigned wbh = smem_u32(sWh) + (nt * 8 + (lane & 7)) * (PWP * 2) + (lane >> 3) * 16;
        unsigned wbl = smem_u32(sWl) + (nt * 8 + (lane & 7)) * (PWP * 2) + (lane >> 3) * 16;
        unsigned bh0[4], bh1[4], bl0[4], bl1[4];
        LDMX4(bh0, wbh);
        LDMX4(bh1, wbh + 64);
        LDMX4(bl0, wbl);
        LDMX4(bl1, wbl + 64);
        mma16816(d[nt], ah[0], bh0 + 0);
        mma16816(d[nt], ah[1], bh0 + 2);
        mma16816(d[nt], ah[2], bh1 + 0);
        mma16816(d[nt], ah[3], bh1 + 2);
        mma16816(d[nt], al[0], bh0 + 0);
        mma16816(d[nt], al[1], bh0 + 2);
        mma16816(d[nt], al[2], bh1 + 0);
        mma16816(d[nt], al[3], bh1 + 2);
        mma16816(d[nt], ah[0], bl0 + 0);
        mma16816(d[nt], ah[1], bl0 + 2);
        mma16816(d[nt], ah[2], bl1 + 0);
        mma16816(d[nt], ah[3], bl1 + 2);
    }

    {
        int r0 = row0 + w * 16 + (lane >> 2);
        int r1 = r0 + 8;
        __half* dh[3] = {g_fh, g_gh, g_hh};
        __half* dl[3] = {g_fl, g_gl, g_hl};
        const float* bias[3] = {bf, bg, bh};
#pragma unroll
        for (int nt = 0; nt < 12; nt++) {
            const int p  = nt >> 2;
            int c  = (nt & 3) * 8 + (lane & 3) * 2;
            float b0 = bias[p][c], b1 = bias[p][c + 1];
            unsigned hi, lo;
            cvt_pair(d[nt][0] + b0, d[nt][1] + b1, hi, lo);
            *(unsigned*)(dh[p] + (size_t)r0 * CB + c) = hi;
            *(unsigned*)(dl[p] + (size_t)r0 * CB + c) = lo;
            cvt_pair(d[nt][2] + b0, d[nt][3] + b1, hi, lo);
            *(unsigned*)(dh[p] + (size_t)r1 * CB + c) = hi;
            *(unsigned*)(dl[p] + (size_t)r1 * CB + c) = lo;
        }
    }
}

// ---------------------------------------------------------------------------
// Kernel 2: flash attention, fp16 split: GEMM1 3-pass, GEMM2 2-pass
// ---------------------------------------------------------------------------
__global__ __launch_bounds__(256, 2) void attn_kernel()
{
    extern __shared__ __align__(16) unsigned char smem[];
    const unsigned sbase = smem_u32(smem);

    const int b  = blockIdx.y;
    const int q0 = blockIdx.x * QT;
    const int k0 = blockIdx.z * (NTOK / SPLITS);
    const int t  = threadIdx.x;
    const int w  = t >> 5;
    const int lane = t & 31;

    const int qrow = t >> 1, qhalf = t & 1;
    const int krow = t >> 2, kq = t & 3;
    const size_t qoff = (size_t)(b * NTOK + q0 + qrow) * CB + qhalf * 16;
    const unsigned qdH = sbase + OFF_QH + qrow * KPB + qhalf * 32;
    const unsigned qdL = sbase + OFF_QL + qrow * KPB + qhalf * 32;

    cp16(qdH,      g_gh + qoff);
    cp16(qdH + 16, g_gh + qoff + 8);
    cp16(qdL,      g_gl + qoff);
    cp16(qdL + 16, g_gl + qoff + 8);
    {
        size_t goff = (size_t)(b * NTOK + k0 + krow) * CB + kq * 8;
        unsigned so = sbase + OFF_BUF + krow * KPB + kq * 16;
        cp16(so + BKH, g_fh + goff);
        cp16(so + BKL, g_fl + goff);
        cp16(so + BVH, g_hh + goff);
        cp16(so + BVL, g_hl + goff);
    }
    CP_COMMIT();
    {
        size_t goff = (size_t)(b * NTOK + k0 + KTILE + krow) * CB + kq * 8;
        unsigned so = sbase + OFF_BUF + BUF_SZ + krow * KPB + kq * 16;
        cp16(so + BKH, g_fh + goff);
        cp16(so + BKL, g_fl + goff);
        cp16(so + BVH, g_hh + goff);
        cp16(so + BVL, g_hl + goff);
    }
    CP_COMMIT();

    unsigned qh[2][4], ql[2][4];
    float m0 = -1e30f, m1 = -1e30f, l0 = 0.f, l1 = 0.f;
    float o[4][4];
#pragma unroll
    for (int nn = 0; nn < 4; nn++)
#pragma unroll
        for (int j = 0; j < 4; j++) o[nn][j] = 0.f;

    for (int kt = 0; kt < KTILES; kt++) {
        CP_WAIT1();
        __syncthreads();

        if (kt == 0) {
            unsigned qa = sbase + OFF_QH + (w * 16 + (lane & 15)) * KPB + (lane >> 4) * 16;
            unsigned qb = sbase + OFF_QL + (w * 16 + (lane & 15)) * KPB + (lane >> 4) * 16;
            LDMX4(qh[0], qa);
            LDMX4(qh[1], qa + 32);
            LDMX4(ql[0], qb);
            LDMX4(ql[1], qb + 32);
        }

        const unsigned bufb = sbase + OFF_BUF + (kt & 1) * BUF_SZ;
        const unsigned kaddr_h = bufb + BKH + (lane & 7) * KPB + (lane >> 3) * 16;
        const unsigned kaddr_l = bufb + BKL + (lane & 7) * KPB + (lane >> 3) * 16;
        const unsigned vbase_h = bufb + BVH + lane * KPB;
        const unsigned vbase_l = bufb + BVL + lane * KPB;

        // ---- GEMM1: S = Q . K^T (3-pass fp16 split) ----------------------
        float s[8][4];
#pragma unroll
        for (int n = 0; n < 8; n++) {
            s[n][0] = s[n][1] = s[n][2] = s[n][3] = 0.f;
            unsigned kh[4], kl[4];
            LDMX4(kh, kaddr_h + n * 8 * KPB);
            LDMX4(kl, kaddr_l + n * 8 * KPB);
            mma16816(s[n], qh[0], kh + 0);
            mma16816(s[n], qh[1], kh + 2);
            mma16816(s[n], ql[0], kh + 0);
            mma16816(s[n], ql[1], kh + 2);
            mma16816(s[n], qh[0], kl + 0);
            mma16816(s[n], qh[1], kl + 2);
        }

        // ---- Online softmax ----------------------------------------------
        float r0 = -1e30f, r1 = -1e30f;
#pragma unroll
        for (int n = 0; n < 8; n++) {
            r0 = fmaxf(r0, fmaxf(s[n][0], s[n][1]));
            r1 = fmaxf(r1, fmaxf(s[n][2], s[n][3]));
        }
        r0 = fmaxf(r0, __shfl_xor_sync(0xffffffffu, r0, 1));
        r0 = fmaxf(r0, __shfl_xor_sync(0xffffffffu, r0, 2));
        r1 = fmaxf(r1, __shfl_xor_sync(0xffffffffu, r1, 1));
        r1 = fmaxf(r1, __shfl_xor_sync(0xffffffffu, r1, 2));
        float mn0 = fmaxf(m0, r0), mn1 = fmaxf(m1, r1);
        float al0 = __expf(m0 - mn0), al1 = __expf(m1 - mn1);

        float ps0 = 0.f, ps1 = 0.f;
        unsigned ph[4][4];          // P in fp16 only (single precision level)
#pragma unroll
        for (int n = 0; n < 8; n++) {
            float p0 = __expf(s[n][0] - mn0);
            float p1 = __expf(s[n][1] - mn0);
            float p2 = __expf(s[n][2] - mn1);
            float p3 = __expf(s[n][3] - mn1);
            ps0 += p0 + p1;  ps1 += p2 + p3;
            int kk = n >> 1, hset = (n & 1) * 2;
            __half2 hp0 = __floats2half2_rn(p0, p1);
            __half2 hp1 = __floats2half2_rn(p2, p3);
            ph[kk][hset + 0] = *(unsigned*)&hp0;
            ph[kk][hset + 1] = *(unsigned*)&hp1;
        }
        ps0 += __shfl_xor_sync(0xffffffffu, ps0, 1);
        ps0 += __shfl_xor_sync(0xffffffffu, ps0, 2);
        ps1 += __shfl_xor_sync(0xffffffffu, ps1, 1);
        ps1 += __shfl_xor_sync(0xffffffffu, ps1, 2);
        l0 = l0 * al0 + ps0;  l1 = l1 * al1 + ps1;
        m0 = mn0;  m1 = mn1;

#pragma unroll
        for (int nn = 0; nn < 4; nn++) {
            o[nn][0] *= al0; o[nn][1] *= al0;
            o[nn][2] *= al1; o[nn][3] *= al1;
        }

        // ---- GEMM2: O += P . (Vh + Vl)  (2-pass: P fp16, V split) --------
#pragma unroll
        for (int kkp = 0; kkp < 2; kkp++) {
            int kk0 = kkp * 2, kk1 = kkp * 2 + 1;
#pragma unroll
            for (int nn = 0; nn < 4; nn++) {
                unsigned vh[4], vl[4];
                unsigned off = (unsigned)(kkp * 32 * KPB + nn * 16);
                LDMX4T(vh, vbase_h + off);
                LDMX4T(vl, vbase_l + off);
                mma16816(o[nn], ph[kk0], vh + 0);
                mma16816(o[nn], ph[kk1], vh + 2);
                mma16816(o[nn], ph[kk0], vl + 0);
                mma16816(o[nn], ph[kk1], vl + 2);
            }
        }

        __syncthreads();
        if (kt + 2 < KTILES) {
            size_t goff = (size_t)(b * NTOK + k0 + (kt + 2) * KTILE + krow) * CB + kq * 8;
            unsigned so = bufb + krow * KPB + kq * 16;
            cp16(so + BKH, g_fh + goff);
            cp16(so + BKL, g_fl + goff);
            cp16(so + BVH, g_hh + goff);
            cp16(so + BVL, g_hl + goff);
        }
        CP_COMMIT();
    }

    {
        int z = blockIdx.z;
        int r = lane >> 2;
        int c = (lane & 3) * 2;
        int grow0 = b * NTOK + q0 + w * 16 + r;
        int grow1 = grow0 + 8;
        if ((lane & 3) == 0) {
            g_m[z][grow0] = m0;  g_l[z][grow0] = l0;
            g_m[z][grow1] = m1;  g_l[z][grow1] = l1;
        }
#pragma unroll
        for (int nn = 0; nn < 4; nn++) {
            *(float2*)&g_part[z][(size_t)grow0 * CB + nn * 8 + c] = make_float2(o[nn][0], o[nn][1]);
            *(float2*)&g_part[z][(size_t)grow1 * CB + nn * 8 + c] = make_float2(o[nn][2], o[nn][3]);
        }
    }
}

// ---------------------------------------------------------------------------
// Kernel 3: fused combine(4 splits) + output projection + residual
// ---------------------------------------------------------------------------
__global__ __launch_bounds__(256) void outc_kernel(
    const float* __restrict__ x,
    const float* __restrict__ Wo, const float* __restrict__ bo,
    const float* __restrict__ gamma,
    float* __restrict__ out)
{
    int idx = blockIdx.x * blockDim.x + threadIdx.x;
    int row = idx >> 5;
    int sub = idx & 31;
    int c4  = (sub & 15) * 4;
    int kh  = sub >> 4;

    float mz[SPLITS], lz[SPLITS];
    float M = -1e30f;
#pragma unroll
    for (int z = 0; z < SPLITS; z++) {
        mz[z] = g_m[z][row];
        lz[z] = g_l[z][row];
        M = fmaxf(M, mz[z]);
    }
    float wz[SPLITS];
    float denom = 0.f;
#pragma unroll
    for (int z = 0; z < SPLITS; z++) {
        wz[z] = __expf(mz[z] - M);
        denom += lz[z] * wz[z];
    }
    float inv = 1.0f / denom;
#pragma unroll
    for (int z = 0; z < SPLITS; z++) wz[z] *= inv;

    float4 o = make_float4(0.f, 0.f, 0.f, 0.f);
#pragma unroll
    for (int j4 = 0; j4 < 4; j4++) {
        float bs[4] = {0.f, 0.f, 0.f, 0.f};
#pragma unroll
        for (int z = 0; z < SPLITS; z++) {
            float4 a = *(const float4*)(&g_part[z][0] + (size_t)row * CB + kh * 16 + j4 * 4);
            bs[0] += a.x * wz[z];
            bs[1] += a.y * wz[z];
            bs[2] += a.z * wz[z];
            bs[3] += a.w * wz[z];
        }
#pragma unroll
        for (int j = 0; j < 4; j++) {
            float4 wv = *(const float4*)(Wo + (kh * 16 + j4 * 4 + j) * CIN + c4);
            o.x = fmaf(bs[j], wv.x, o.x);
            o.y = fmaf(bs[j], wv.y, o.y);
            o.z = fmaf(bs[j], wv.z, o.z);
            o.w = fmaf(bs[j], wv.w, o.w);
        }
    }
    o.x += __shfl_xor_sync(0xffffffffu, o.x, 16);
    o.y += __shfl_xor_sync(0xffffffffu, o.y, 16);
    o.z += __shfl_xor_sync(0xffffffffu, o.z, 16);
    o.w += __shfl_xor_sync(0xffffffffu, o.w, 16);

    if (kh == 0) {
        float gm = gamma[0];
        float4 bv = *(const float4*)(bo + c4);
        float4 xv = *(const float4*)(x + (size_t)row * CIN + c4);
        float4 r;
        r.x = xv.x + gm * (o.x + bv.x);
        r.y = xv.y + gm * (o.y + bv.y);
        r.z = xv.z + gm * (o.z + bv.z);
        r.w = xv.w + gm * (o.w + bv.w);
        *(float4*)(out + (size_t)row * CIN + c4) = r;
    }
}

// ---------------------------------------------------------------------------
extern "C" void kernel_launch(void* const* d_in, const int* in_sizes, int n_in,
                              void* d_out, int out_size)
{
    const float* x     = (const float*)d_in[0];
    const float* Wf    = (const float*)d_in[1];
    const float* bf    = (const float*)d_in[2];
    const float* Wg    = (const float*)d_in[3];
    const float* bg    = (const float*)d_in[4];
    const float* Wh    = (const float*)d_in[5];
    const float* bh    = (const float*)d_in[6];
    const float* Wo    = (const float*)d_in[7];
    const float* bo    = (const float*)d_in[8];
    const float* gamma = (const float*)d_in[9];
    float* out = (float*)d_out;
    (void)in_sizes; (void)n_in; (void)out_size;

    cudaFuncSetAttribute(attn_kernel,
                         cudaFuncAttributeMaxDynamicSharedMemorySize, SMEM_BYTES);

    proj_mma_kernel<<<BATCH * NTOK / PROWS, 128>>>(x, Wf, bf, Wg, bg, Wh, bh);

    dim3 agrid(NTOK / QT, BATCH, SPLITS);
    attn_kernel<<<agrid, 256, SMEM_BYTES>>>();

    outc_kernel<<<BATCH * NTOK * 32 / 256, 256>>>(x, Wo, bo, gamma, out);
}

// round 9
// speedup vs baseline: 1.6353x; 1.2291x over previous
#include <cuda_runtime.h>
#include <cuda_fp16.h>

// ---------------------------------------------------------------------------
// Problem constants
// ---------------------------------------------------------------------------
#define NTOK 4096
#define CB   32
#define CIN  64
#define BATCH 2

#define QT     128                     // queries per block (8 warps x 16 rows)
#define KTILE  64                      // keys per tile
#define SPLITS 4
#define KTILES (NTOK / SPLITS / KTILE) // 16
#define KP     40                      // padded row stride (fp16 elems)
#define KPB    80                      // padded row stride bytes

// attn dynamic SMEM layout (bytes): Q hi/lo kept; K/V hi only (residuals dropped)
#define OFF_QH   0
#define OFF_QL   10240
#define OFF_BUF  20480
#define BUF_SZ   10240
#define BKH      0
#define BVH      5120
#define SMEM_BYTES (OFF_BUF + 2 * BUF_SZ)   // 40960 (x2 blocks/SM = 80KB)

// proj tiling
#define PROWS 64
#define PWP   72                       // padded row stride (fp16) = 144B
#define NPROJ 96

// ---------------------------------------------------------------------------
// Scratch (no cudaMalloc allowed)
// ---------------------------------------------------------------------------
__device__ __align__(16) __half g_gh[BATCH * NTOK * CB];   // Q hi
__device__ __align__(16) __half g_gl[BATCH * NTOK * CB];   // Q lo (kept: GEMM1 2nd pass)
__device__ __align__(16) __half g_fh[BATCH * NTOK * CB];   // K hi
__device__ __align__(16) __half g_hh[BATCH * NTOK * CB];   // V hi
__device__ __align__(16) float g_part[SPLITS][BATCH * NTOK * CB];
__device__ __align__(16) float g_m[SPLITS][BATCH * NTOK];
__device__ __align__(16) float g_l[SPLITS][BATCH * NTOK];

// ---------------------------------------------------------------------------
// Helpers
// ---------------------------------------------------------------------------
__device__ __forceinline__ unsigned smem_u32(const void* p) {
    unsigned a;
    asm("{ .reg .u64 t; cvta.to.shared.u64 t, %1; cvt.u32.u64 %0, t; }"
        : "=r"(a) : "l"(p));
    return a;
}
__device__ __forceinline__ void cp16(unsigned dst, const void* src) {
    asm volatile("cp.async.cg.shared.global [%0], [%1], 16;"
                 :: "r"(dst), "l"(src) : "memory");
}
#define CP_COMMIT() asm volatile("cp.async.commit_group;" ::: "memory")
#define CP_WAIT1()  asm volatile("cp.async.wait_group 1;" ::: "memory")

#define LDMX4(r, a) \
    asm volatile("ldmatrix.sync.aligned.m8n8.x4.shared.b16 {%0,%1,%2,%3}, [%4];" \
        : "=r"((r)[0]), "=r"((r)[1]), "=r"((r)[2]), "=r"((r)[3]) : "r"(a))
#define LDMX4T(r, a) \
    asm volatile("ldmatrix.sync.aligned.m8n8.x4.trans.shared.b16 {%0,%1,%2,%3}, [%4];" \
        : "=r"((r)[0]), "=r"((r)[1]), "=r"((r)[2]), "=r"((r)[3]) : "r"(a))

__device__ __forceinline__ void mma16816(float* d, const unsigned* a, const unsigned* b) {
    asm volatile(
        "mma.sync.aligned.m16n8k16.row.col.f32.f16.f16.f32 "
        "{%0,%1,%2,%3}, {%4,%5,%6,%7}, {%8,%9}, {%0,%1,%2,%3};"
        : "+f"(d[0]), "+f"(d[1]), "+f"(d[2]), "+f"(d[3])
        : "r"(a[0]), "r"(a[1]), "r"(a[2]), "r"(a[3]), "r"(b[0]), "r"(b[1]));
}

__device__ __forceinline__ void cvt_pair(float f0, float f1, unsigned& hi, unsigned& lo) {
    __half2 h = __floats2half2_rn(f0, f1);
    float r0 = f0 - __low2float(h);
    float r1 = f1 - __high2float(h);
    __half2 l = __floats2half2_rn(r0, r1);
    hi = *(unsigned*)&h;
    lo = *(unsigned*)&l;
}
__device__ __forceinline__ void cvt1(float f, __half& h, __half& l) {
    h = __float2half_rn(f);
    l = __float2half_rn(f - __half2float(h));
}

// ---------------------------------------------------------------------------
// Kernel 1: projections as one HMMA GEMM: [B*N x 64] @ [64 x 96] + bias
// (full 3-pass split internally; only Q gets a stored residual)
// ---------------------------------------------------------------------------
__global__ __launch_bounds__(128) void proj_mma_kernel(
    const float* __restrict__ x,
    const float* __restrict__ Wf, const float* __restrict__ bf,
    const float* __restrict__ Wg, const float* __restrict__ bg,
    const float* __restrict__ Wh, const float* __restrict__ bh)
{
    __shared__ __half sXh[PROWS * PWP], sXl[PROWS * PWP];
    __shared__ __half sWh[NPROJ * PWP], sWl[NPROJ * PWP];

    const int t    = threadIdx.x;
    const int w    = t >> 5;
    const int lane = t & 31;
    const int row0 = blockIdx.x * PROWS;

    {
        int r = t >> 1, half = t & 1;
        const float4* src = (const float4*)(x + (size_t)(row0 + r) * CIN + half * 32);
        int e = r * PWP + half * 32;
#pragma unroll
        for (int i = 0; i < 8; i++) {
            float4 v = src[i];
            unsigned h0, l0, h1, l1;
            cvt_pair(v.x, v.y, h0, l0);
            cvt_pair(v.z, v.w, h1, l1);
            *(uint2*)(sXh + e + i * 4) = make_uint2(h0, h1);
            *(uint2*)(sXl + e + i * 4) = make_uint2(l0, l1);
        }
    }

    {
        const float* Ws[3] = {Wf, Wg, Wh};
#pragma unroll
        for (int it = 0; it < 12; it++) {
            int i = t + it * 128;
            int p = i >> 9;
            int rr = i & 511;
            int k = rr >> 3;
            int c = (rr & 7) * 4;
            float4 v = *(const float4*)(Ws[p] + k * CB + c);
            int cb = p * CB + c;
            __half h, l;
            cvt1(v.x, h, l);
            sWh[(cb + 0) * PWP + k] = h;  sWl[(cb + 0) * PWP + k] = l;
            cvt1(v.y, h, l);
            sWh[(cb + 1) * PWP + k] = h;  sWl[(cb + 1) * PWP + k] = l;
            cvt1(v.z, h, l);
            sWh[(cb + 2) * PWP + k] = h;  sWl[(cb + 2) * PWP + k] = l;
            cvt1(v.w, h, l);
            sWh[(cb + 3) * PWP + k] = h;  sWl[(cb + 3) * PWP + k] = l;
        }
    }
    __syncthreads();

    unsigned ah[4][4], al[4][4];
    {
        unsigned xa = smem_u32(sXh) + (w * 16 + (lane & 15)) * (PWP * 2) + (lane >> 4) * 16;
        unsigned xb = smem_u32(sXl) + (w * 16 + (lane & 15)) * (PWP * 2) + (lane >> 4) * 16;
#pragma unroll
        for (int ks = 0; ks < 4; ks++) {
            LDMX4(ah[ks], xa + ks * 32);
            LDMX4(al[ks], xb + ks * 32);
        }
    }

    float d[12][4];
#pragma unroll
    for (int nt = 0; nt < 12; nt++) {
        d[nt][0] = d[nt][1] = d[nt][2] = d[nt][3] = 0.f;
        unsigned wbh = smem_u32(sWh) + (nt * 8 + (lane & 7)) * (PWP * 2) + (lane >> 3) * 16;
        unsigned wbl = smem_u32(sWl) + (nt * 8 + (lane & 7)) * (PWP * 2) + (lane >> 3) * 16;
        unsigned bh0[4], bh1[4], bl0[4], bl1[4];
        LDMX4(bh0, wbh);
        LDMX4(bh1, wbh + 64);
        LDMX4(bl0, wbl);
        LDMX4(bl1, wbl + 64);
        mma16816(d[nt], ah[0], bh0 + 0);
        mma16816(d[nt], ah[1], bh0 + 2);
        mma16816(d[nt], ah[2], bh1 + 0);
        mma16816(d[nt], ah[3], bh1 + 2);
        mma16816(d[nt], al[0], bh0 + 0);
        mma16816(d[nt], al[1], bh0 + 2);
        mma16816(d[nt], al[2], bh1 + 0);
        mma16816(d[nt], al[3], bh1 + 2);
        mma16816(d[nt], ah[0], bl0 + 0);
        mma16816(d[nt], ah[1], bl0 + 2);
        mma16816(d[nt], ah[2], bl1 + 0);
        mma16816(d[nt], ah[3], bl1 + 2);
    }

    {
        int r0 = row0 + w * 16 + (lane >> 2);
        int r1 = r0 + 8;
        __half* dh[3] = {g_fh, g_gh, g_hh};
        const float* bias[3] = {bf, bg, bh};
#pragma unroll
        for (int nt = 0; nt < 12; nt++) {
            const int p  = nt >> 2;
            int c  = (nt & 3) * 8 + (lane & 3) * 2;
            float b0 = bias[p][c], b1 = bias[p][c + 1];
            unsigned hi, lo;
            cvt_pair(d[nt][0] + b0, d[nt][1] + b1, hi, lo);
            *(unsigned*)(dh[p] + (size_t)r0 * CB + c) = hi;
            if (p == 1) *(unsigned*)(g_gl + (size_t)r0 * CB + c) = lo;
            cvt_pair(d[nt][2] + b0, d[nt][3] + b1, hi, lo);
            *(unsigned*)(dh[p] + (size_t)r1 * CB + c) = hi;
            if (p == 1) *(unsigned*)(g_gl + (size_t)r1 * CB + c) = lo;
        }
    }
}

// ---------------------------------------------------------------------------
// Kernel 2: flash attention — GEMM1 2-pass (qh.kh + ql.kh), GEMM2 1-pass
// ---------------------------------------------------------------------------
__global__ __launch_bounds__(256, 2) void attn_kernel()
{
    extern __shared__ __align__(16) unsigned char smem[];
    const unsigned sbase = smem_u32(smem);

    const int b  = blockIdx.y;
    const int q0 = blockIdx.x * QT;
    const int k0 = blockIdx.z * (NTOK / SPLITS);
    const int t  = threadIdx.x;
    const int w  = t >> 5;
    const int lane = t & 31;

    const int qrow = t >> 1, qhalf = t & 1;
    const int krow = t >> 2, kq = t & 3;
    const size_t qoff = (size_t)(b * NTOK + q0 + qrow) * CB + qhalf * 16;
    const unsigned qdH = sbase + OFF_QH + qrow * KPB + qhalf * 32;
    const unsigned qdL = sbase + OFF_QL + qrow * KPB + qhalf * 32;

    cp16(qdH,      g_gh + qoff);
    cp16(qdH + 16, g_gh + qoff + 8);
    cp16(qdL,      g_gl + qoff);
    cp16(qdL + 16, g_gl + qoff + 8);
    {
        size_t goff = (size_t)(b * NTOK + k0 + krow) * CB + kq * 8;
        unsigned so = sbase + OFF_BUF + krow * KPB + kq * 16;
        cp16(so + BKH, g_fh + goff);
        cp16(so + BVH, g_hh + goff);
    }
    CP_COMMIT();
    {
        size_t goff = (size_t)(b * NTOK + k0 + KTILE + krow) * CB + kq * 8;
        unsigned so = sbase + OFF_BUF + BUF_SZ + krow * KPB + kq * 16;
        cp16(so + BKH, g_fh + goff);
        cp16(so + BVH, g_hh + goff);
    }
    CP_COMMIT();

    unsigned qh[2][4], ql[2][4];
    float m0 = -1e30f, m1 = -1e30f, l0 = 0.f, l1 = 0.f;
    float o[4][4];
#pragma unroll
    for (int nn = 0; nn < 4; nn++)
#pragma unroll
        for (int j = 0; j < 4; j++) o[nn][j] = 0.f;

    for (int kt = 0; kt < KTILES; kt++) {
        CP_WAIT1();
        __syncthreads();

        if (kt == 0) {
            unsigned qa = sbase + OFF_QH + (w * 16 + (lane & 15)) * KPB + (lane >> 4) * 16;
            unsigned qb = sbase + OFF_QL + (w * 16 + (lane & 15)) * KPB + (lane >> 4) * 16;
            LDMX4(qh[0], qa);
            LDMX4(qh[1], qa + 32);
            LDMX4(ql[0], qb);
            LDMX4(ql[1], qb + 32);
        }

        const unsigned bufb = sbase + OFF_BUF + (kt & 1) * BUF_SZ;
        const unsigned kaddr_h = bufb + BKH + (lane & 7) * KPB + (lane >> 3) * 16;
        const unsigned vbase_h = bufb + BVH + lane * KPB;

        // ---- GEMM1: S = Q . K^T (2-pass: qh.kh + ql.kh) ------------------
        float s[8][4];
#pragma unroll
        for (int n = 0; n < 8; n++) {
            s[n][0] = s[n][1] = s[n][2] = s[n][3] = 0.f;
            unsigned kh[4];
            LDMX4(kh, kaddr_h + n * 8 * KPB);
            mma16816(s[n], qh[0], kh + 0);
            mma16816(s[n], qh[1], kh + 2);
            mma16816(s[n], ql[0], kh + 0);
            mma16816(s[n], ql[1], kh + 2);
        }

        // ---- Online softmax ----------------------------------------------
        float r0 = -1e30f, r1 = -1e30f;
#pragma unroll
        for (int n = 0; n < 8; n++) {
            r0 = fmaxf(r0, fmaxf(s[n][0], s[n][1]));
            r1 = fmaxf(r1, fmaxf(s[n][2], s[n][3]));
        }
        r0 = fmaxf(r0, __shfl_xor_sync(0xffffffffu, r0, 1));
        r0 = fmaxf(r0, __shfl_xor_sync(0xffffffffu, r0, 2));
        r1 = fmaxf(r1, __shfl_xor_sync(0xffffffffu, r1, 1));
        r1 = fmaxf(r1, __shfl_xor_sync(0xffffffffu, r1, 2));
        float mn0 = fmaxf(m0, r0), mn1 = fmaxf(m1, r1);
        float al0 = __expf(m0 - mn0), al1 = __expf(m1 - mn1);

        float ps0 = 0.f, ps1 = 0.f;
        unsigned ph[4][4];
#pragma unroll
        for (int n = 0; n < 8; n++) {
            float p0 = __expf(s[n][0] - mn0);
            float p1 = __expf(s[n][1] - mn0);
            float p2 = __expf(s[n][2] - mn1);
            float p3 = __expf(s[n][3] - mn1);
            ps0 += p0 + p1;  ps1 += p2 + p3;
            int kk = n >> 1, hset = (n & 1) * 2;
            __half2 hp0 = __floats2half2_rn(p0, p1);
            __half2 hp1 = __floats2half2_rn(p2, p3);
            ph[kk][hset + 0] = *(unsigned*)&hp0;
            ph[kk][hset + 1] = *(unsigned*)&hp1;
        }
        ps0 += __shfl_xor_sync(0xffffffffu, ps0, 1);
        ps0 += __shfl_xor_sync(0xffffffffu, ps0, 2);
        ps1 += __shfl_xor_sync(0xffffffffu, ps1, 1);
        ps1 += __shfl_xor_sync(0xffffffffu, ps1, 2);
        l0 = l0 * al0 + ps0;  l1 = l1 * al1 + ps1;
        m0 = mn0;  m1 = mn1;

#pragma unroll
        for (int nn = 0; nn < 4; nn++) {
            o[nn][0] *= al0; o[nn][1] *= al0;
            o[nn][2] *= al1; o[nn][3] *= al1;
        }

        // ---- GEMM2: O += P . Vh  (1-pass) --------------------------------
#pragma unroll
        for (int kkp = 0; kkp < 2; kkp++) {
            int kk0 = kkp * 2, kk1 = kkp * 2 + 1;
#pragma unroll
            for (int nn = 0; nn < 4; nn++) {
                unsigned vh[4];
                unsigned off = (unsigned)(kkp * 32 * KPB + nn * 16);
                LDMX4T(vh, vbase_h + off);
                mma16816(o[nn], ph[kk0], vh + 0);
                mma16816(o[nn], ph[kk1], vh + 2);
            }
        }

        __syncthreads();
        if (kt + 2 < KTILES) {
            size_t goff = (size_t)(b * NTOK + k0 + (kt + 2) * KTILE + krow) * CB + kq * 8;
            unsigned so = bufb + krow * KPB + kq * 16;
            cp16(so + BKH, g_fh + goff);
            cp16(so + BVH, g_hh + goff);
        }
        CP_COMMIT();
    }

    {
        int z = blockIdx.z;
        int r = lane >> 2;
        int c = (lane & 3) * 2;
        int grow0 = b * NTOK + q0 + w * 16 + r;
        int grow1 = grow0 + 8;
        if ((lane & 3) == 0) {
            g_m[z][grow0] = m0;  g_l[z][grow0] = l0;
            g_m[z][grow1] = m1;  g_l[z][grow1] = l1;
        }
#pragma unroll
        for (int nn = 0; nn < 4; nn++) {
            *(float2*)&g_part[z][(size_t)grow0 * CB + nn * 8 + c] = make_float2(o[nn][0], o[nn][1]);
            *(float2*)&g_part[z][(size_t)grow1 * CB + nn * 8 + c] = make_float2(o[nn][2], o[nn][3]);
        }
    }
}

// ---------------------------------------------------------------------------
// Kernel 3: fused combine(4 splits) + output projection + residual
// ---------------------------------------------------------------------------
__global__ __launch_bounds__(256) void outc_kernel(
    const float* __restrict__ x,
    const float* __restrict__ Wo, const float* __restrict__ bo,
    const float* __restrict__ gamma,
    float* __restrict__ out)
{
    int idx = blockIdx.x * blockDim.x + threadIdx.x;
    int row = idx >> 5;
    int sub = idx & 31;
    int c4  = (sub & 15) * 4;
    int kh  = sub >> 4;

    float mz[SPLITS], lz[SPLITS];
    float M = -1e30f;
#pragma unroll
    for (int z = 0; z < SPLITS; z++) {
        mz[z] = g_m[z][row];
        lz[z] = g_l[z][row];
        M = fmaxf(M, mz[z]);
    }
    float wz[SPLITS];
    float denom = 0.f;
#pragma unroll
    for (int z = 0; z < SPLITS; z++) {
        wz[z] = __expf(mz[z] - M);
        denom += lz[z] * wz[z];
    }
    float inv = 1.0f / denom;
#pragma unroll
    for (int z = 0; z < SPLITS; z++) wz[z] *= inv;

    float4 o = make_float4(0.f, 0.f, 0.f, 0.f);
#pragma unroll
    for (int j4 = 0; j4 < 4; j4++) {
        float bs[4] = {0.f, 0.f, 0.f, 0.f};
#pragma unroll
        for (int z = 0; z < SPLITS; z++) {
            float4 a = *(const float4*)(&g_part[z][0] + (size_t)row * CB + kh * 16 + j4 * 4);
            bs[0] += a.x * wz[z];
            bs[1] += a.y * wz[z];
            bs[2] += a.z * wz[z];
            bs[3] += a.w * wz[z];
        }
#pragma unroll
        for (int j = 0; j < 4; j++) {
            float4 wv = *(const float4*)(Wo + (kh * 16 + j4 * 4 + j) * CIN + c4);
            o.x = fmaf(bs[j], wv.x, o.x);
            o.y = fmaf(bs[j], wv.y, o.y);
            o.z = fmaf(bs[j], wv.z, o.z);
            o.w = fmaf(bs[j], wv.w, o.w);
        }
    }
    o.x += __shfl_xor_sync(0xffffffffu, o.x, 16);
    o.y += __shfl_xor_sync(0xffffffffu, o.y, 16);
    o.z += __shfl_xor_sync(0xffffffffu, o.z, 16);
    o.w += __shfl_xor_sync(0xffffffffu, o.w, 16);

    if (kh == 0) {
        float gm = gamma[0];
        float4 bv = *(const float4*)(bo + c4);
        float4 xv = *(const float4*)(x + (size_t)row * CIN + c4);
        float4 r;
        r.x = xv.x + gm * (o.x + bv.x);
        r.y = xv.y + gm * (o.y + bv.y);
        r.z = xv.z + gm * (o.z + bv.z);
        r.w = xv.w + gm * (o.w + bv.w);
        *(float4*)(out + (size_t)row * CIN + c4) = r;
    }
}

// ---------------------------------------------------------------------------
extern "C" void kernel_launch(void* const* d_in, const int* in_sizes, int n_in,
                              void* d_out, int out_size)
{
    const float* x     = (const float*)d_in[0];
    const float* Wf    = (const float*)d_in[1];
    const float* bf    = (const float*)d_in[2];
    const float* Wg    = (const float*)d_in[3];
    const float* bg    = (const float*)d_in[4];
    const float* Wh    = (const float*)d_in[5];
    const float* bh    = (const float*)d_in[6];
    const float* Wo    = (const float*)d_in[7];
    const float* bo    = (const float*)d_in[8];
    const float* gamma = (const float*)d_in[9];
    float* out = (float*)d_out;
    (void)in_sizes; (void)n_in; (void)out_size;

    cudaFuncSetAttribute(attn_kernel,
                         cudaFuncAttributeMaxDynamicSharedMemorySize, SMEM_BYTES);

    proj_mma_kernel<<<BATCH * NTOK / PROWS, 128>>>(x, Wf, bf, Wg, bg, Wh, bh);

    dim3 agrid(NTOK / QT, BATCH, SPLITS);
    attn_kernel<<<agrid, 256, SMEM_BYTES>>>();

    outc_kernel<<<BATCH * NTOK * 32 / 256, 256>>>(x, Wo, bo, gamma, out);
}